// round 3
// baseline (speedup 1.0000x reference)
#include <cuda_runtime.h>
#include <math.h>

#define NB 16
#define NN 512
#define NMAT (NB*NN)   /* 8192 matrices */
#define NSWEEP 8

/* ------------- device scratch (allocation-free) ------------- */
__device__ float g_C[3*1024];          /* Cayley matrices Cq,Ck,Cv */
__device__ float g_qf[(size_t)NMAT*1024];
__device__ float g_kf[(size_t)NMAT*1024];
__device__ float g_vf[(size_t)NMAT*1024];
__device__ float g_q2[NMAT];
__device__ float g_k2[NMAT];
__device__ float g_E[(size_t)NB*NN*NN];  /* exp(scores)[b][j][i] */
__device__ float g_D[NMAT];              /* col sums D[b*512+i]  */

/* ------------- kernel A: Cayley maps C = (I-X)(I+X)^-1, X = W - W^T ------------- */
__global__ void cayley_kernel(const float* __restrict__ Wq,
                              const float* __restrict__ Wk,
                              const float* __restrict__ Wv) {
    const int w = blockIdx.x;
    const float* W = (w == 0) ? Wq : (w == 1) ? Wk : Wv;
    __shared__ float M[32][64];   /* augmented [I+X | I] */
    __shared__ float X[32][32];
    __shared__ float fac[32];
    __shared__ float pivv;
    __shared__ int   pivi;
    const int t = threadIdx.x;    /* 64 threads */

    for (int e = t; e < 1024; e += 64) {
        int i = e >> 5, j = e & 31;
        float xv = W[i*32 + j] - W[j*32 + i];
        X[i][j] = xv;
        M[i][j]      = ((i == j) ? 1.f : 0.f) + xv;
        M[i][j + 32] = (i == j) ? 1.f : 0.f;
    }
    __syncthreads();

    for (int k = 0; k < 32; ++k) {
        if (t == 0) {
            float best = -1.f; int bi = k;
            for (int i = k; i < 32; ++i) {
                float v = fabsf(M[i][k]);
                if (v > best) { best = v; bi = i; }
            }
            pivi = bi;
        }
        __syncthreads();
        int pi = pivi;
        if (pi != k) { float tmp = M[k][t]; M[k][t] = M[pi][t]; M[pi][t] = tmp; }
        __syncthreads();
        if (t == 0) pivv = M[k][k];
        __syncthreads();
        float pv = pivv;
        M[k][t] /= pv;
        __syncthreads();
        if (t < 32) fac[t] = M[t][k];
        __syncthreads();
        for (int i = 0; i < 32; ++i)
            if (i != k) M[i][t] -= fac[i] * M[k][t];
        __syncthreads();
    }

    /* C = Minv - X @ Minv */
    for (int e = t; e < 1024; e += 64) {
        int i = e >> 5, j = e & 31;
        float acc = M[i][32 + j];
        #pragma unroll
        for (int kk = 0; kk < 32; ++kk) acc -= X[i][kk] * M[kk][32 + j];
        g_C[w*1024 + e] = acc;
    }
}

/* ------------- kernel B: Jacobi logm + 3 congruence transforms ------------- */
__global__ __launch_bounds__(512)
void logm_transform_kernel(const float* __restrict__ x) {
    __shared__ float A[32][33];
    __shared__ float Vv[32][33];
    __shared__ float S[32][33];
    __shared__ float Cs[32][33];
    __shared__ float lw[32];
    __shared__ float ssq;

    const int mat  = blockIdx.x;
    const int tid  = threadIdx.x;
    const int warp = tid >> 5;   /* 0..15 : pair index */
    const int lane = tid & 31;
    const float* xin = x + (size_t)mat * 1024;

    for (int e = tid; e < 1024; e += 512) {
        int i = e >> 5, j = e & 31;
        A[i][j]  = xin[e];
        Vv[i][j] = (i == j) ? 1.f : 0.f;
    }
    __syncthreads();

    for (int sw = 0; sw < NSWEEP; ++sw) {
        for (int r = 0; r < 31; ++r) {
            int a, b;
            if (warp == 0) { a = r % 31; b = 31; }
            else { a = (r + warp) % 31; b = (r + 31 - warp) % 31; }
            int p = (a < b) ? a : b;
            int q = (a < b) ? b : a;

            float c = 1.f, s = 0.f;
            if (lane == 0) {
                float app = A[p][p], aqq = A[q][q], apq = A[p][q];
                if (apq != 0.f) {
                    float tau = (aqq - app) / (2.f * apq);
                    float tt  = ((tau >= 0.f) ? 1.f : -1.f) /
                                (fabsf(tau) + sqrtf(1.f + tau*tau));
                    c = rsqrtf(1.f + tt*tt);
                    s = tt * c;
                }
            }
            c = __shfl_sync(0xffffffffu, c, 0);
            s = __shfl_sync(0xffffffffu, s, 0);

            /* row phase: warp owns rows p,q exclusively */
            float ap = A[p][lane], aq = A[q][lane];
            A[p][lane] = c*ap - s*aq;
            A[q][lane] = s*ap + c*aq;
            __syncthreads();
            /* col phase: warp owns cols p,q exclusively (+ eigvecs) */
            float bp = A[lane][p], bq = A[lane][q];
            A[lane][p] = c*bp - s*bq;
            A[lane][q] = s*bp + c*bq;
            float vp = Vv[lane][p], vq = Vv[lane][q];
            Vv[lane][p] = c*vp - s*vq;
            Vv[lane][q] = s*vp + c*vq;
            __syncthreads();
        }
    }

    if (tid < 32) lw[tid] = logf(A[tid][tid]);
    __syncthreads();

    /* S = V diag(log w) V^T, zero diagonal (= olm_diffeo) */
    for (int e = tid; e < 1024; e += 512) {
        int i = e >> 5, j = e & 31;
        float acc = 0.f;
        #pragma unroll
        for (int kk = 0; kk < 32; ++kk) acc += Vv[i][kk] * lw[kk] * Vv[j][kk];
        S[i][j] = (i == j) ? 0.f : acc;
    }
    __syncthreads();

    for (int wsel = 0; wsel < 3; ++wsel) {
        for (int e = tid; e < 1024; e += 512)
            Cs[e >> 5][e & 31] = g_C[wsel*1024 + e];
        if (tid == 0) ssq = 0.f;
        __syncthreads();
        /* T = C @ S  -> Vv (dead after S built) */
        for (int e = tid; e < 1024; e += 512) {
            int i = e >> 5, j = e & 31;
            float acc = 0.f;
            #pragma unroll
            for (int kk = 0; kk < 32; ++kk) acc += Cs[i][kk] * S[kk][j];
            Vv[i][j] = acc;
        }
        __syncthreads();
        /* Y = T @ C^T, zero diag, write flat + sumsq */
        float* gout = (wsel == 0) ? g_qf : (wsel == 1) ? g_kf : g_vf;
        float local = 0.f;
        for (int e = tid; e < 1024; e += 512) {
            int i = e >> 5, j = e & 31;
            float acc = 0.f;
            #pragma unroll
            for (int kk = 0; kk < 32; ++kk) acc += Vv[i][kk] * Cs[j][kk];
            if (i == j) acc = 0.f;
            gout[(size_t)mat*1024 + e] = acc;
            local += acc * acc;
        }
        if (wsel < 2) {
            #pragma unroll
            for (int off = 16; off; off >>= 1)
                local += __shfl_down_sync(0xffffffffu, local, off);
            if (lane == 0) atomicAdd(&ssq, local);
        }
        __syncthreads();
        if (wsel < 2 && tid == 0)
            ((wsel == 0) ? g_q2 : g_k2)[mat] = ssq;
        __syncthreads();
    }
}

/* ------------- kernel: zero D ------------- */
__global__ void zeroD_kernel() {
    int i = blockIdx.x * blockDim.x + threadIdx.x;
    if (i < NMAT) g_D[i] = 0.f;
}

/* ------------- kernel C: E[b,j,i] = exp(score), D[b,i] = sum_j E ------------- */
__global__ __launch_bounds__(256)
void score_kernel() {
    const int b  = blockIdx.z;
    const int i0 = blockIdx.x * 64;
    const int j0 = blockIdx.y * 64;
    __shared__ float Ks[16][65];
    __shared__ float Qs[16][65];
    __shared__ float scol[64];
    const int tid = threadIdx.x;
    const int tx = tid & 15, ty = tid >> 4;
    const int lr = tid >> 2, lc = tid & 3;

    float acc[4][4];
    #pragma unroll
    for (int m = 0; m < 4; ++m)
        #pragma unroll
        for (int n = 0; n < 4; ++n) acc[m][n] = 0.f;

    if (tid < 64) scol[tid] = 0.f;

    const float* kp = g_kf + ((size_t)(b*512 + j0 + lr))*1024 + lc*4;
    const float* qp = g_qf + ((size_t)(b*512 + i0 + lr))*1024 + lc*4;

    for (int k0 = 0; k0 < 1024; k0 += 16) {
        float4 kv = *(const float4*)(kp + k0);
        float4 qv = *(const float4*)(qp + k0);
        Ks[lc*4+0][lr] = kv.x; Ks[lc*4+1][lr] = kv.y;
        Ks[lc*4+2][lr] = kv.z; Ks[lc*4+3][lr] = kv.w;
        Qs[lc*4+0][lr] = qv.x; Qs[lc*4+1][lr] = qv.y;
        Qs[lc*4+2][lr] = qv.z; Qs[lc*4+3][lr] = qv.w;
        __syncthreads();
        #pragma unroll
        for (int kk = 0; kk < 16; ++kk) {
            float am[4], bn[4];
            #pragma unroll
            for (int m = 0; m < 4; ++m) am[m] = Ks[kk][ty*4 + m];
            #pragma unroll
            for (int n = 0; n < 4; ++n) bn[n] = Qs[kk][tx*4 + n];
            #pragma unroll
            for (int m = 0; m < 4; ++m)
                #pragma unroll
                for (int n = 0; n < 4; ++n) acc[m][n] += am[m] * bn[n];
        }
        __syncthreads();
    }

    float q2c[4], k2r[4];
    #pragma unroll
    for (int n = 0; n < 4; ++n) q2c[n] = g_q2[b*512 + i0 + tx*4 + n];
    #pragma unroll
    for (int m = 0; m < 4; ++m) k2r[m] = g_k2[b*512 + j0 + ty*4 + m];

    #pragma unroll
    for (int n = 0; n < 4; ++n) {
        float colpart = 0.f;
        #pragma unroll
        for (int m = 0; m < 4; ++m) {
            float d2 = k2r[m] + q2c[n] - 2.f * acc[m][n];
            d2 = fmaxf(d2, 1e-12f);
            float en = sqrtf(d2);
            float sc = 1.f / (1.f + log1pf(en));
            float ev = expf(sc);
            g_E[((size_t)b*512 + j0 + ty*4 + m)*512 + i0 + tx*4 + n] = ev;
            colpart += ev;
        }
        atomicAdd(&scol[tx*4 + n], colpart);
    }
    __syncthreads();
    if (tid < 64) atomicAdd(&g_D[b*512 + i0 + tid], scol[tid]);
}

/* ------------- kernel: fold 1/D into V rows ------------- */
__global__ void scaleV_kernel() {
    int m = blockIdx.x;
    float r = 1.f / g_D[m];
    float* v = g_vf + (size_t)m * 1024;
    for (int f = threadIdx.x; f < 1024; f += 256) v[f] *= r;
}

/* ------------- kernel D: out[b,c,f] = sum_a E[b,c,a] * v'[b,a,f] ------------- */
__global__ __launch_bounds__(256)
void out_kernel(float* __restrict__ out) {
    const int b  = blockIdx.z;
    const int c0 = blockIdx.x * 64;
    const int f0 = blockIdx.y * 64;
    __shared__ float Es[64][33];
    __shared__ __align__(16) float Vs[32][68];
    const int tid = threadIdx.x;
    const int tx = tid & 15, ty = tid >> 4;
    const int lrE = tid >> 2, lcE = tid & 3;
    const int lrV = tid >> 3, lcV = tid & 7;

    float acc[4][4];
    #pragma unroll
    for (int m = 0; m < 4; ++m)
        #pragma unroll
        for (int n = 0; n < 4; ++n) acc[m][n] = 0.f;

    for (int a0 = 0; a0 < 512; a0 += 32) {
        const float* ep = g_E + ((size_t)b*512 + c0 + lrE)*512 + a0;
        float4 e0 = *(const float4*)(ep + lcE*4);
        float4 e1 = *(const float4*)(ep + (lcE + 4)*4);
        Es[lrE][lcE*4+0] = e0.x; Es[lrE][lcE*4+1] = e0.y;
        Es[lrE][lcE*4+2] = e0.z; Es[lrE][lcE*4+3] = e0.w;
        Es[lrE][(lcE+4)*4+0] = e1.x; Es[lrE][(lcE+4)*4+1] = e1.y;
        Es[lrE][(lcE+4)*4+2] = e1.z; Es[lrE][(lcE+4)*4+3] = e1.w;
        /* V tile is 32(a) x 64(f): each thread loads TWO float4s
           (cols lcV*4 and lcV*4+32) -- previous round only loaded the
           first 32 columns, leaving Vs[..][32..63] uninitialized. */
        const float* vp = g_vf + ((size_t)(b*512 + a0 + lrV))*1024 + f0 + lcV*4;
        *(float4*)&Vs[lrV][lcV*4]      = *(const float4*)vp;
        *(float4*)&Vs[lrV][lcV*4 + 32] = *(const float4*)(vp + 32);
        __syncthreads();
        #pragma unroll
        for (int aa = 0; aa < 32; ++aa) {
            float am[4];
            #pragma unroll
            for (int m = 0; m < 4; ++m) am[m] = Es[ty*4 + m][aa];
            float4 bv = *(const float4*)&Vs[aa][tx*4];
            #pragma unroll
            for (int m = 0; m < 4; ++m) {
                acc[m][0] += am[m] * bv.x;
                acc[m][1] += am[m] * bv.y;
                acc[m][2] += am[m] * bv.z;
                acc[m][3] += am[m] * bv.w;
            }
        }
        __syncthreads();
    }

    #pragma unroll
    for (int m = 0; m < 4; ++m) {
        float4 o;
        o.x = acc[m][0]; o.y = acc[m][1]; o.z = acc[m][2]; o.w = acc[m][3];
        *(float4*)&out[((size_t)b*512 + c0 + ty*4 + m)*1024 + f0 + tx*4] = o;
    }
}

/* ------------- launch ------------- */
extern "C" void kernel_launch(void* const* d_in, const int* in_sizes, int n_in,
                              void* d_out, int out_size) {
    const float* x  = (const float*)d_in[0];
    const float* wq = (const float*)d_in[1];
    const float* wk = (const float*)d_in[2];
    const float* wv = (const float*)d_in[3];
    float* out = (float*)d_out;

    cayley_kernel<<<3, 64>>>(wq, wk, wv);
    logm_transform_kernel<<<NMAT, 512>>>(x);
    zeroD_kernel<<<NMAT/256, 256>>>();
    score_kernel<<<dim3(8, 8, NB), 256>>>();
    scaleV_kernel<<<NMAT, 256>>>();
    out_kernel<<<dim3(8, 16, NB), 256>>>(out);
}

// round 4
// speedup vs baseline: 5.3293x; 5.3293x over previous
#include <cuda_runtime.h>
#include <math.h>

#define NB 16
#define NN 512
#define NMAT (NB*NN)   /* 8192 matrices */
#define NSWEEP 8
#define WPB 4          /* matrices (warps) per block in jacobi kernel */

/* ------------- device scratch (allocation-free) ------------- */
__device__ float g_C[3*1024];          /* Cayley matrices Cq,Ck,Cv */
__device__ float g_qf[(size_t)NMAT*1024];
__device__ float g_kf[(size_t)NMAT*1024];
__device__ float g_vf[(size_t)NMAT*1024];
__device__ float g_q2[NMAT];
__device__ float g_k2[NMAT];
__device__ float g_E[(size_t)NB*NN*NN];  /* exp(scores)[b][j][i] */
__device__ float g_D[NMAT];              /* col sums D[b*512+i]  */

/* ------------- kernel A: Cayley maps C = (I-X)(I+X)^-1, X = W - W^T ------------- */
__global__ void cayley_kernel(const float* __restrict__ Wq,
                              const float* __restrict__ Wk,
                              const float* __restrict__ Wv) {
    const int w = blockIdx.x;
    const float* W = (w == 0) ? Wq : (w == 1) ? Wk : Wv;
    __shared__ float M[32][64];   /* augmented [I+X | I] */
    __shared__ float X[32][32];
    __shared__ float fac[32];
    __shared__ float pivv;
    __shared__ int   pivi;
    const int t = threadIdx.x;    /* 64 threads */

    for (int e = t; e < 1024; e += 64) {
        int i = e >> 5, j = e & 31;
        float xv = W[i*32 + j] - W[j*32 + i];
        X[i][j] = xv;
        M[i][j]      = ((i == j) ? 1.f : 0.f) + xv;
        M[i][j + 32] = (i == j) ? 1.f : 0.f;
    }
    __syncthreads();

    for (int k = 0; k < 32; ++k) {
        if (t == 0) {
            float best = -1.f; int bi = k;
            for (int i = k; i < 32; ++i) {
                float v = fabsf(M[i][k]);
                if (v > best) { best = v; bi = i; }
            }
            pivi = bi;
        }
        __syncthreads();
        int pi = pivi;
        if (pi != k) { float tmp = M[k][t]; M[k][t] = M[pi][t]; M[pi][t] = tmp; }
        __syncthreads();
        if (t == 0) pivv = M[k][k];
        __syncthreads();
        float pv = pivv;
        M[k][t] /= pv;
        __syncthreads();
        if (t < 32) fac[t] = M[t][k];
        __syncthreads();
        for (int i = 0; i < 32; ++i)
            if (i != k) M[i][t] -= fac[i] * M[k][t];
        __syncthreads();
    }

    /* C = Minv - X @ Minv */
    for (int e = t; e < 1024; e += 64) {
        int i = e >> 5, j = e & 31;
        float acc = M[i][32 + j];
        #pragma unroll
        for (int kk = 0; kk < 32; ++kk) acc -= X[i][kk] * M[kk][32 + j];
        g_C[w*1024 + e] = acc;
    }
}

/* ------------- kernel B: warp-per-matrix one-sided Jacobi logm + transforms -------------
   SPD A = Q L Q^T. One-sided (Hestenes) Jacobi orthogonalizes the COLUMNS of A
   by right rotations only; at convergence column j = lambda_j * q_j. So:
   lambda_j = ||b_j||, and S = sum_j (log(lambda_j)/lambda_j^2) b_j b_j^T.
   Lane j owns column j in registers -> zero barriers in the iteration. */
__global__ __launch_bounds__(WPB*32)
void logm_transform_kernel(const float* __restrict__ x) {
    __shared__ float Bsh[WPB][32][33];
    __shared__ float Ssh[WPB][32][33];
    __shared__ float Cs[3][32][33];
    __shared__ float wsh[WPB][32];

    const int tid  = threadIdx.x;
    const int wp   = tid >> 5;
    const int lane = tid & 31;
    const int mat  = blockIdx.x * WPB + wp;

    /* load the 3 Cayley matrices (block-shared, padded) */
    for (int e = tid; e < 3*1024; e += WPB*32) {
        int w = e >> 10, r = (e >> 5) & 31, cjj = e & 31;
        Cs[w][r][cjj] = g_C[e];
    }
    __syncthreads();

    /* lane j loads column j of A (A symmetric: col j = row j, read transposed
       for coalescing: at step i all lanes read consecutive addresses) */
    const float* xin = x + (size_t)mat * 1024;
    float b[32];
    #pragma unroll
    for (int i = 0; i < 32; ++i) b[i] = xin[i*32 + lane];

    float pb[32];
    for (int sw = 0; sw < NSWEEP; ++sw) {
        for (int r = 0; r < 31; ++r) {
            /* round-robin tournament pairing */
            int partner;
            if (lane == 31) partner = r;
            else {
                partner = (2*r + 31 - lane) % 31;
                if (partner == lane) partner = 31;
            }

            float sn = 0.f, cross = 0.f;
            #pragma unroll
            for (int i = 0; i < 32; ++i) {
                pb[i]  = __shfl_sync(0xffffffffu, b[i], partner);
                sn     = fmaf(b[i], b[i], sn);
                cross  = fmaf(b[i], pb[i], cross);
            }
            float pn = __shfl_sync(0xffffffffu, sn, partner);

            bool isp = lane < partner;             /* lane is the 'p' column */
            float delta = isp ? (pn - sn) : (sn - pn);   /* a_qq - a_pp, identical bits on both lanes */

            float c = 1.f, s = 0.f;
            if (cross != 0.f) {
                float tau = delta / (2.f * cross);
                float tt  = copysignf(1.f, tau) / (fabsf(tau) + sqrtf(fmaf(tau, tau, 1.f)));
                c = rsqrtf(fmaf(tt, tt, 1.f));
                s = tt * c;
            }
            float ssgn = isp ? -s : s;
            #pragma unroll
            for (int i = 0; i < 32; ++i)
                b[i] = fmaf(c, b[i], ssgn * pb[i]);
        }
    }

    /* eigenvalues + weights */
    float sn = 0.f;
    #pragma unroll
    for (int i = 0; i < 32; ++i) sn = fmaf(b[i], b[i], sn);
    float lam = sqrtf(sn);
    float wgt = logf(lam) / sn;          /* log(lambda)/lambda^2 */

    #pragma unroll
    for (int i = 0; i < 32; ++i) Bsh[wp][i][lane] = b[i];
    wsh[wp][lane] = wgt;
    __syncwarp();

    /* S[l][k] = sum_j w_j B[l][j] B[k][j], zero diagonal (lane l = row l) */
    float rw[32];
    #pragma unroll
    for (int j = 0; j < 32; ++j) rw[j] = wsh[wp][j] * Bsh[wp][lane][j];
    #pragma unroll
    for (int k = 0; k < 32; ++k) {
        float acc = 0.f;
        #pragma unroll
        for (int j = 0; j < 32; ++j) acc = fmaf(rw[j], Bsh[wp][k][j], acc);
        Ssh[wp][lane][k] = (k == lane) ? 0.f : acc;
    }
    __syncwarp();

    /* 3 congruence transforms Y = C S C^T, zero diag, write + sumsq */
    #pragma unroll 1
    for (int wsel = 0; wsel < 3; ++wsel) {
        float crow[32];
        #pragma unroll
        for (int m = 0; m < 32; ++m) crow[m] = Cs[wsel][lane][m];

        float t[32];
        #pragma unroll
        for (int k = 0; k < 32; ++k) {
            float acc = 0.f;
            #pragma unroll
            for (int m = 0; m < 32; ++m) acc = fmaf(crow[m], Ssh[wp][m][k], acc);
            t[k] = acc;
        }

        float ss = 0.f;
        #pragma unroll
        for (int k = 0; k < 32; ++k) {
            float acc = 0.f;
            #pragma unroll
            for (int m = 0; m < 32; ++m) acc = fmaf(t[m], Cs[wsel][k][m], acc);
            if (k == lane) acc = 0.f;
            ss = fmaf(acc, acc, ss);
            Bsh[wp][lane][k] = acc;        /* stage row for coalesced write */
        }
        __syncwarp();

        float* gout = (wsel == 0) ? g_qf : (wsel == 1) ? g_kf : g_vf;
        #pragma unroll
        for (int i = 0; i < 32; ++i)
            gout[(size_t)mat*1024 + i*32 + lane] = Bsh[wp][i][lane];

        if (wsel < 2) {
            #pragma unroll
            for (int off = 16; off; off >>= 1)
                ss += __shfl_down_sync(0xffffffffu, ss, off);
            if (lane == 0) ((wsel == 0) ? g_q2 : g_k2)[mat] = ss;
        }
        __syncwarp();
    }
}

/* ------------- kernel: zero D ------------- */
__global__ void zeroD_kernel() {
    int i = blockIdx.x * blockDim.x + threadIdx.x;
    if (i < NMAT) g_D[i] = 0.f;
}

/* ------------- kernel C: E[b,j,i] = exp(score), D[b,i] = sum_j E ------------- */
__global__ __launch_bounds__(256)
void score_kernel() {
    const int b  = blockIdx.z;
    const int i0 = blockIdx.x * 64;
    const int j0 = blockIdx.y * 64;
    __shared__ float Ks[16][65];
    __shared__ float Qs[16][65];
    __shared__ float scol[64];
    const int tid = threadIdx.x;
    const int tx = tid & 15, ty = tid >> 4;
    const int lr = tid >> 2, lc = tid & 3;

    float acc[4][4];
    #pragma unroll
    for (int m = 0; m < 4; ++m)
        #pragma unroll
        for (int n = 0; n < 4; ++n) acc[m][n] = 0.f;

    if (tid < 64) scol[tid] = 0.f;

    const float* kp = g_kf + ((size_t)(b*512 + j0 + lr))*1024 + lc*4;
    const float* qp = g_qf + ((size_t)(b*512 + i0 + lr))*1024 + lc*4;

    for (int k0 = 0; k0 < 1024; k0 += 16) {
        float4 kv = *(const float4*)(kp + k0);
        float4 qv = *(const float4*)(qp + k0);
        Ks[lc*4+0][lr] = kv.x; Ks[lc*4+1][lr] = kv.y;
        Ks[lc*4+2][lr] = kv.z; Ks[lc*4+3][lr] = kv.w;
        Qs[lc*4+0][lr] = qv.x; Qs[lc*4+1][lr] = qv.y;
        Qs[lc*4+2][lr] = qv.z; Qs[lc*4+3][lr] = qv.w;
        __syncthreads();
        #pragma unroll
        for (int kk = 0; kk < 16; ++kk) {
            float am[4], bn[4];
            #pragma unroll
            for (int m = 0; m < 4; ++m) am[m] = Ks[kk][ty*4 + m];
            #pragma unroll
            for (int n = 0; n < 4; ++n) bn[n] = Qs[kk][tx*4 + n];
            #pragma unroll
            for (int m = 0; m < 4; ++m)
                #pragma unroll
                for (int n = 0; n < 4; ++n) acc[m][n] += am[m] * bn[n];
        }
        __syncthreads();
    }

    float q2c[4], k2r[4];
    #pragma unroll
    for (int n = 0; n < 4; ++n) q2c[n] = g_q2[b*512 + i0 + tx*4 + n];
    #pragma unroll
    for (int m = 0; m < 4; ++m) k2r[m] = g_k2[b*512 + j0 + ty*4 + m];

    #pragma unroll
    for (int n = 0; n < 4; ++n) {
        float colpart = 0.f;
        #pragma unroll
        for (int m = 0; m < 4; ++m) {
            float d2 = k2r[m] + q2c[n] - 2.f * acc[m][n];
            d2 = fmaxf(d2, 1e-12f);
            float en = sqrtf(d2);
            float sc = 1.f / (1.f + log1pf(en));
            float ev = expf(sc);
            g_E[((size_t)b*512 + j0 + ty*4 + m)*512 + i0 + tx*4 + n] = ev;
            colpart += ev;
        }
        atomicAdd(&scol[tx*4 + n], colpart);
    }
    __syncthreads();
    if (tid < 64) atomicAdd(&g_D[b*512 + i0 + tid], scol[tid]);
}

/* ------------- kernel: fold 1/D into V rows ------------- */
__global__ void scaleV_kernel() {
    int m = blockIdx.x;
    float r = 1.f / g_D[m];
    float* v = g_vf + (size_t)m * 1024;
    for (int f = threadIdx.x; f < 1024; f += 256) v[f] *= r;
}

/* ------------- kernel D: out[b,c,f] = sum_a E[b,c,a] * v'[b,a,f] ------------- */
__global__ __launch_bounds__(256)
void out_kernel(float* __restrict__ out) {
    const int b  = blockIdx.z;
    const int c0 = blockIdx.x * 64;
    const int f0 = blockIdx.y * 64;
    __shared__ float Es[64][33];
    __shared__ __align__(16) float Vs[32][68];
    const int tid = threadIdx.x;
    const int tx = tid & 15, ty = tid >> 4;
    const int lrE = tid >> 2, lcE = tid & 3;
    const int lrV = tid >> 3, lcV = tid & 7;

    float acc[4][4];
    #pragma unroll
    for (int m = 0; m < 4; ++m)
        #pragma unroll
        for (int n = 0; n < 4; ++n) acc[m][n] = 0.f;

    for (int a0 = 0; a0 < 512; a0 += 32) {
        const float* ep = g_E + ((size_t)b*512 + c0 + lrE)*512 + a0;
        float4 e0 = *(const float4*)(ep + lcE*4);
        float4 e1 = *(const float4*)(ep + (lcE + 4)*4);
        Es[lrE][lcE*4+0] = e0.x; Es[lrE][lcE*4+1] = e0.y;
        Es[lrE][lcE*4+2] = e0.z; Es[lrE][lcE*4+3] = e0.w;
        Es[lrE][(lcE+4)*4+0] = e1.x; Es[lrE][(lcE+4)*4+1] = e1.y;
        Es[lrE][(lcE+4)*4+2] = e1.z; Es[lrE][(lcE+4)*4+3] = e1.w;
        const float* vp = g_vf + ((size_t)(b*512 + a0 + lrV))*1024 + f0 + lcV*4;
        *(float4*)&Vs[lrV][lcV*4]      = *(const float4*)vp;
        *(float4*)&Vs[lrV][lcV*4 + 32] = *(const float4*)(vp + 32);
        __syncthreads();
        #pragma unroll
        for (int aa = 0; aa < 32; ++aa) {
            float am[4];
            #pragma unroll
            for (int m = 0; m < 4; ++m) am[m] = Es[ty*4 + m][aa];
            float4 bv = *(const float4*)&Vs[aa][tx*4];
            #pragma unroll
            for (int m = 0; m < 4; ++m) {
                acc[m][0] += am[m] * bv.x;
                acc[m][1] += am[m] * bv.y;
                acc[m][2] += am[m] * bv.z;
                acc[m][3] += am[m] * bv.w;
            }
        }
        __syncthreads();
    }

    #pragma unroll
    for (int m = 0; m < 4; ++m) {
        float4 o;
        o.x = acc[m][0]; o.y = acc[m][1]; o.z = acc[m][2]; o.w = acc[m][3];
        *(float4*)&out[((size_t)b*512 + c0 + ty*4 + m)*1024 + f0 + tx*4] = o;
    }
}

/* ------------- launch ------------- */
extern "C" void kernel_launch(void* const* d_in, const int* in_sizes, int n_in,
                              void* d_out, int out_size) {
    const float* x  = (const float*)d_in[0];
    const float* wq = (const float*)d_in[1];
    const float* wk = (const float*)d_in[2];
    const float* wv = (const float*)d_in[3];
    float* out = (float*)d_out;

    cayley_kernel<<<3, 64>>>(wq, wk, wv);
    logm_transform_kernel<<<NMAT/WPB, WPB*32>>>(x);
    zeroD_kernel<<<NMAT/256, 256>>>();
    score_kernel<<<dim3(8, 8, NB), 256>>>();
    scaleV_kernel<<<NMAT, 256>>>();
    out_kernel<<<dim3(8, 16, NB), 256>>>(out);
}

// round 5
// speedup vs baseline: 6.6560x; 1.2489x over previous
#include <cuda_runtime.h>
#include <math.h>

#define NB 16
#define NN 512
#define NMAT (NB*NN)   /* 8192 matrices */
#define NSWEEP 6
#define WPB 4          /* matrices (warps) per block in jacobi kernel */

/* ------------- device scratch (allocation-free) ------------- */
__device__ float g_C[3*1024];          /* Cayley matrices Cq,Ck,Cv */
__device__ float g_qf[(size_t)NMAT*1024];
__device__ float g_kf[(size_t)NMAT*1024];
__device__ float g_vf[(size_t)NMAT*1024];
__device__ float g_q2[NMAT];
__device__ float g_k2[NMAT];
__device__ float g_E[(size_t)NB*NN*NN];  /* exp(scores)[b][j][i] */
__device__ float g_D[NMAT];              /* col sums D[b*512+i]  */

/* ------------- kernel A: Cayley maps C = (I-X)(I+X)^-1, X = W - W^T ------------- */
__global__ void cayley_kernel(const float* __restrict__ Wq,
                              const float* __restrict__ Wk,
                              const float* __restrict__ Wv) {
    const int w = blockIdx.x;
    const float* W = (w == 0) ? Wq : (w == 1) ? Wk : Wv;
    __shared__ float M[32][64];   /* augmented [I+X | I] */
    __shared__ float X[32][32];
    __shared__ float fac[32];
    __shared__ float pivv;
    __shared__ int   pivi;
    const int t = threadIdx.x;    /* 64 threads */

    for (int e = t; e < 1024; e += 64) {
        int i = e >> 5, j = e & 31;
        float xv = W[i*32 + j] - W[j*32 + i];
        X[i][j] = xv;
        M[i][j]      = ((i == j) ? 1.f : 0.f) + xv;
        M[i][j + 32] = (i == j) ? 1.f : 0.f;
    }
    __syncthreads();

    for (int k = 0; k < 32; ++k) {
        if (t == 0) {
            float best = -1.f; int bi = k;
            for (int i = k; i < 32; ++i) {
                float v = fabsf(M[i][k]);
                if (v > best) { best = v; bi = i; }
            }
            pivi = bi;
        }
        __syncthreads();
        int pi = pivi;
        if (pi != k) { float tmp = M[k][t]; M[k][t] = M[pi][t]; M[pi][t] = tmp; }
        __syncthreads();
        if (t == 0) pivv = M[k][k];
        __syncthreads();
        float pv = pivv;
        M[k][t] /= pv;
        __syncthreads();
        if (t < 32) fac[t] = M[t][k];
        __syncthreads();
        for (int i = 0; i < 32; ++i)
            if (i != k) M[i][t] -= fac[i] * M[k][t];
        __syncthreads();
    }

    /* C = Minv - X @ Minv */
    for (int e = t; e < 1024; e += 64) {
        int i = e >> 5, j = e & 31;
        float acc = M[i][32 + j];
        #pragma unroll
        for (int kk = 0; kk < 32; ++kk) acc -= X[i][kk] * M[kk][32 + j];
        g_C[w*1024 + e] = acc;
    }
}

/* ------------- kernel B: warp-per-matrix one-sided Jacobi logm + transforms ------------- */
__global__ __launch_bounds__(WPB*32)
void logm_transform_kernel(const float* __restrict__ x) {
    __shared__ float Bsh[WPB][32][33];
    __shared__ float Ssh[WPB][32][33];
    __shared__ float Cs[3][32][33];
    __shared__ float wsh[WPB][32];

    const int tid  = threadIdx.x;
    const int wp   = tid >> 5;
    const int lane = tid & 31;
    const int mat  = blockIdx.x * WPB + wp;

    for (int e = tid; e < 3*1024; e += WPB*32) {
        int w = e >> 10, r = (e >> 5) & 31, cjj = e & 31;
        Cs[w][r][cjj] = g_C[e];
    }
    __syncthreads();

    const float* xin = x + (size_t)mat * 1024;
    float b[32];
    #pragma unroll
    for (int i = 0; i < 32; ++i) b[i] = xin[i*32 + lane];

    float pb[32];
    for (int sw = 0; sw < NSWEEP; ++sw) {
        for (int r = 0; r < 31; ++r) {
            int partner;
            if (lane == 31) partner = r;
            else {
                partner = (2*r + 31 - lane) % 31;
                if (partner == lane) partner = 31;
            }

            float sn = 0.f, cross = 0.f;
            #pragma unroll
            for (int i = 0; i < 32; ++i) {
                pb[i]  = __shfl_sync(0xffffffffu, b[i], partner);
                sn     = fmaf(b[i], b[i], sn);
                cross  = fmaf(b[i], pb[i], cross);
            }
            float pn = __shfl_sync(0xffffffffu, sn, partner);

            bool isp = lane < partner;
            float delta = isp ? (pn - sn) : (sn - pn);

            float c = 1.f, s = 0.f;
            if (cross != 0.f) {
                float tau = delta / (2.f * cross);
                float tt  = copysignf(1.f, tau) / (fabsf(tau) + sqrtf(fmaf(tau, tau, 1.f)));
                c = rsqrtf(fmaf(tt, tt, 1.f));
                s = tt * c;
            }
            float ssgn = isp ? -s : s;
            #pragma unroll
            for (int i = 0; i < 32; ++i)
                b[i] = fmaf(c, b[i], ssgn * pb[i]);
        }
    }

    float sn = 0.f;
    #pragma unroll
    for (int i = 0; i < 32; ++i) sn = fmaf(b[i], b[i], sn);
    float lam = sqrtf(sn);
    float wgt = logf(lam) / sn;

    #pragma unroll
    for (int i = 0; i < 32; ++i) Bsh[wp][i][lane] = b[i];
    wsh[wp][lane] = wgt;
    __syncwarp();

    float rw[32];
    #pragma unroll
    for (int j = 0; j < 32; ++j) rw[j] = wsh[wp][j] * Bsh[wp][lane][j];
    #pragma unroll
    for (int k = 0; k < 32; ++k) {
        float acc = 0.f;
        #pragma unroll
        for (int j = 0; j < 32; ++j) acc = fmaf(rw[j], Bsh[wp][k][j], acc);
        Ssh[wp][lane][k] = (k == lane) ? 0.f : acc;
    }
    __syncwarp();

    #pragma unroll 1
    for (int wsel = 0; wsel < 3; ++wsel) {
        float crow[32];
        #pragma unroll
        for (int m = 0; m < 32; ++m) crow[m] = Cs[wsel][lane][m];

        float t[32];
        #pragma unroll
        for (int k = 0; k < 32; ++k) {
            float acc = 0.f;
            #pragma unroll
            for (int m = 0; m < 32; ++m) acc = fmaf(crow[m], Ssh[wp][m][k], acc);
            t[k] = acc;
        }

        float ss = 0.f;
        #pragma unroll
        for (int k = 0; k < 32; ++k) {
            float acc = 0.f;
            #pragma unroll
            for (int m = 0; m < 32; ++m) acc = fmaf(t[m], Cs[wsel][k][m], acc);
            if (k == lane) acc = 0.f;
            ss = fmaf(acc, acc, ss);
            Bsh[wp][lane][k] = acc;
        }
        __syncwarp();

        float* gout = (wsel == 0) ? g_qf : (wsel == 1) ? g_kf : g_vf;
        #pragma unroll
        for (int i = 0; i < 32; ++i)
            gout[(size_t)mat*1024 + i*32 + lane] = Bsh[wp][i][lane];

        if (wsel < 2) {
            #pragma unroll
            for (int off = 16; off; off >>= 1)
                ss += __shfl_down_sync(0xffffffffu, ss, off);
            if (lane == 0) ((wsel == 0) ? g_q2 : g_k2)[mat] = ss;
        }
        __syncwarp();
    }
}

/* ------------- kernel: zero D ------------- */
__global__ void zeroD_kernel() {
    int i = blockIdx.x * blockDim.x + threadIdx.x;
    if (i < NMAT) g_D[i] = 0.f;
}

/* ------------- kernel C: 128x128 tile, 8x8/thread. E[b,j,i]=exp(score), D[b,i]=sum_j ------------- */
__global__ __launch_bounds__(256, 2)
void score_kernel() {
    const int b  = blockIdx.z;
    const int i0 = blockIdx.x * 128;
    const int j0 = blockIdx.y * 128;
    __shared__ float Ks[8][132];   /* [k][j], pad 132 (16B-aligned rows, conflict-free) */
    __shared__ float Qs[8][132];   /* [k][i] */
    __shared__ float scol[128];
    const int tid = threadIdx.x;
    const int tx = tid & 15, ty = tid >> 4;   /* tx -> i dir, ty -> j dir */
    const int lr = tid >> 1;                  /* load row 0..127 */
    const int lk = (tid & 1) * 4;             /* k offset 0/4 */

    float acc[8][8];
    #pragma unroll
    for (int m = 0; m < 8; ++m)
        #pragma unroll
        for (int n = 0; n < 8; ++n) acc[m][n] = 0.f;
    if (tid < 128) scol[tid] = 0.f;

    const float* kp = g_kf + ((size_t)(b*512 + j0 + lr))*1024 + lk;
    const float* qp = g_qf + ((size_t)(b*512 + i0 + lr))*1024 + lk;

    for (int k0 = 0; k0 < 1024; k0 += 8) {
        float4 kv = *(const float4*)(kp + k0);
        float4 qv = *(const float4*)(qp + k0);
        __syncthreads();
        Ks[lk+0][lr] = kv.x; Ks[lk+1][lr] = kv.y; Ks[lk+2][lr] = kv.z; Ks[lk+3][lr] = kv.w;
        Qs[lk+0][lr] = qv.x; Qs[lk+1][lr] = qv.y; Qs[lk+2][lr] = qv.z; Qs[lk+3][lr] = qv.w;
        __syncthreads();
        #pragma unroll
        for (int kk = 0; kk < 8; ++kk) {
            float4 a0 = *(const float4*)&Qs[kk][tx*4];
            float4 a1 = *(const float4*)&Qs[kk][tx*4 + 64];
            float4 b0 = *(const float4*)&Ks[kk][ty*4];
            float4 b1 = *(const float4*)&Ks[kk][ty*4 + 64];
            float av[8] = {a0.x,a0.y,a0.z,a0.w,a1.x,a1.y,a1.z,a1.w};
            float bv[8] = {b0.x,b0.y,b0.z,b0.w,b1.x,b1.y,b1.z,b1.w};
            #pragma unroll
            for (int m = 0; m < 8; ++m)
                #pragma unroll
                for (int n = 0; n < 8; ++n)
                    acc[m][n] = fmaf(bv[m], av[n], acc[m][n]);
        }
    }

    float q2c[8], k2r[8];
    #pragma unroll
    for (int n = 0; n < 8; ++n)
        q2c[n] = g_q2[b*512 + i0 + tx*4 + (n & 3) + (n >> 2)*64];
    #pragma unroll
    for (int m = 0; m < 8; ++m)
        k2r[m] = g_k2[b*512 + j0 + ty*4 + (m & 3) + (m >> 2)*64];

    float csum[8];
    #pragma unroll
    for (int n = 0; n < 8; ++n) csum[n] = 0.f;

    #pragma unroll
    for (int m = 0; m < 8; ++m) {
        int j = j0 + ty*4 + (m & 3) + (m >> 2)*64;
        float ev[8];
        #pragma unroll
        for (int n = 0; n < 8; ++n) {
            float d2 = k2r[m] + q2c[n] - 2.f * acc[m][n];
            d2 = fmaxf(d2, 1e-12f);
            float en = sqrtf(d2);
            float sc = 1.f / (1.f + log1pf(en));
            ev[n] = expf(sc);
            csum[n] += ev[n];
        }
        float* ep = g_E + ((size_t)b*512 + j)*512 + i0 + tx*4;
        float4 o0; o0.x = ev[0]; o0.y = ev[1]; o0.z = ev[2]; o0.w = ev[3];
        float4 o1; o1.x = ev[4]; o1.y = ev[5]; o1.z = ev[6]; o1.w = ev[7];
        *(float4*)ep = o0;
        *(float4*)(ep + 64) = o1;
    }

    #pragma unroll
    for (int n = 0; n < 8; ++n)
        atomicAdd(&scol[tx*4 + (n & 3) + (n >> 2)*64], csum[n]);
    __syncthreads();
    if (tid < 128) atomicAdd(&g_D[b*512 + i0 + tid], scol[tid]);
}

/* ------------- kernel: fold 1/D into V rows ------------- */
__global__ void scaleV_kernel() {
    int m = blockIdx.x;
    float r = 1.f / g_D[m];
    float* v = g_vf + (size_t)m * 1024;
    for (int f = threadIdx.x; f < 1024; f += 256) v[f] *= r;
}

/* ------------- kernel D: 128x128 tile, 8x8/thread. out[b,c,f] = sum_a E[b,c,a]*v'[b,a,f] ------------- */
__global__ __launch_bounds__(256, 2)
void out_kernel(float* __restrict__ out) {
    const int b  = blockIdx.z;
    const int c0 = blockIdx.x * 128;
    const int f0 = blockIdx.y * 128;
    __shared__ float As[8][132];   /* [a][c] */
    __shared__ float Bs[8][132];   /* [a][f] */
    const int tid = threadIdx.x;
    const int tx = tid & 15, ty = tid >> 4;   /* tx -> f dir, ty -> c dir */
    const int lr = tid >> 1;                  /* A load row (c) */
    const int lk = (tid & 1) * 4;             /* A load a-offset */
    const int la = tid >> 5;                  /* B load row (a) 0..7 */
    const int lf = (tid & 31) * 4;            /* B load col (f) */

    float acc[8][8];
    #pragma unroll
    for (int m = 0; m < 8; ++m)
        #pragma unroll
        for (int n = 0; n < 8; ++n) acc[m][n] = 0.f;

    const float* ep = g_E  + ((size_t)b*512 + c0 + lr)*512 + lk;
    const float* vp = g_vf + ((size_t)b*512 + la)*1024 + f0 + lf;

    for (int a0 = 0; a0 < 512; a0 += 8) {
        float4 av = *(const float4*)(ep + a0);
        float4 bvl = *(const float4*)(vp + (size_t)a0*1024);
        __syncthreads();
        As[lk+0][lr] = av.x; As[lk+1][lr] = av.y; As[lk+2][lr] = av.z; As[lk+3][lr] = av.w;
        *(float4*)&Bs[la][lf] = bvl;
        __syncthreads();
        #pragma unroll
        for (int kk = 0; kk < 8; ++kk) {
            float4 c0v = *(const float4*)&As[kk][ty*4];
            float4 c1v = *(const float4*)&As[kk][ty*4 + 64];
            float4 f0v = *(const float4*)&Bs[kk][tx*4];
            float4 f1v = *(const float4*)&Bs[kk][tx*4 + 64];
            float cm[8] = {c0v.x,c0v.y,c0v.z,c0v.w,c1v.x,c1v.y,c1v.z,c1v.w};
            float fn[8] = {f0v.x,f0v.y,f0v.z,f0v.w,f1v.x,f1v.y,f1v.z,f1v.w};
            #pragma unroll
            for (int m = 0; m < 8; ++m)
                #pragma unroll
                for (int n = 0; n < 8; ++n)
                    acc[m][n] = fmaf(cm[m], fn[n], acc[m][n]);
        }
    }

    #pragma unroll
    for (int m = 0; m < 8; ++m) {
        int c = c0 + ty*4 + (m & 3) + (m >> 2)*64;
        float* op = out + ((size_t)b*512 + c)*1024 + f0 + tx*4;
        float4 o0; o0.x = acc[m][0]; o0.y = acc[m][1]; o0.z = acc[m][2]; o0.w = acc[m][3];
        float4 o1; o1.x = acc[m][4]; o1.y = acc[m][5]; o1.z = acc[m][6]; o1.w = acc[m][7];
        *(float4*)op = o0;
        *(float4*)(op + 64) = o1;
    }
}

/* ------------- launch ------------- */
extern "C" void kernel_launch(void* const* d_in, const int* in_sizes, int n_in,
                              void* d_out, int out_size) {
    const float* x  = (const float*)d_in[0];
    const float* wq = (const float*)d_in[1];
    const float* wk = (const float*)d_in[2];
    const float* wv = (const float*)d_in[3];
    float* out = (float*)d_out;

    cayley_kernel<<<3, 64>>>(wq, wk, wv);
    logm_transform_kernel<<<NMAT/WPB, WPB*32>>>(x);
    zeroD_kernel<<<NMAT/256, 256>>>();
    score_kernel<<<dim3(4, 4, NB), 256>>>();
    scaleV_kernel<<<NMAT, 256>>>();
    out_kernel<<<dim3(4, 8, NB), 256>>>(out);
}

// round 7
// speedup vs baseline: 6.7020x; 1.0069x over previous
#include <cuda_runtime.h>
#include <math.h>

#define NB 16
#define NN 512
#define NMAT (NB*NN)   /* 8192 matrices */
#define NSWEEP 6
#define WPB 4          /* matrices (warps) per block in jacobi kernel */

/* ------------- device scratch (allocation-free) ------------- */
__device__ float g_C[3*1024];          /* Cayley matrices Cq,Ck,Cv */
__device__ float g_qf[(size_t)NMAT*1024];
__device__ float g_kf[(size_t)NMAT*1024];
__device__ float g_vf[(size_t)NMAT*1024];
__device__ float g_q2[NMAT];
__device__ float g_k2[NMAT];
__device__ float g_E[(size_t)NB*NN*NN];  /* exp(scores)[b][j][i] */
__device__ float g_D[NMAT];              /* col sums D[b*512+i]  */
__device__ float g_rD[NMAT];             /* 1/D */

/* ------------- kernel A: Cayley maps C = (I-X)(I+X)^-1, X = W - W^T ------------- */
__global__ void cayley_kernel(const float* __restrict__ Wq,
                              const float* __restrict__ Wk,
                              const float* __restrict__ Wv) {
    const int w = blockIdx.x;
    const float* W = (w == 0) ? Wq : (w == 1) ? Wk : Wv;
    __shared__ float M[32][64];
    __shared__ float X[32][32];
    __shared__ float fac[32];
    __shared__ float pivv;
    __shared__ int   pivi;
    const int t = threadIdx.x;    /* 64 threads */

    for (int e = t; e < 1024; e += 64) {
        int i = e >> 5, j = e & 31;
        float xv = W[i*32 + j] - W[j*32 + i];
        X[i][j] = xv;
        M[i][j]      = ((i == j) ? 1.f : 0.f) + xv;
        M[i][j + 32] = (i == j) ? 1.f : 0.f;
    }
    __syncthreads();

    for (int k = 0; k < 32; ++k) {
        if (t == 0) {
            float best = -1.f; int bi = k;
            for (int i = k; i < 32; ++i) {
                float v = fabsf(M[i][k]);
                if (v > best) { best = v; bi = i; }
            }
            pivi = bi;
        }
        __syncthreads();
        int pi = pivi;
        if (pi != k) { float tmp = M[k][t]; M[k][t] = M[pi][t]; M[pi][t] = tmp; }
        __syncthreads();
        if (t == 0) pivv = M[k][k];
        __syncthreads();
        float pv = pivv;
        M[k][t] /= pv;
        __syncthreads();
        if (t < 32) fac[t] = M[t][k];
        __syncthreads();
        for (int i = 0; i < 32; ++i)
            if (i != k) M[i][t] -= fac[i] * M[k][t];
        __syncthreads();
    }

    for (int e = t; e < 1024; e += 64) {
        int i = e >> 5, j = e & 31;
        float acc = M[i][32 + j];
        #pragma unroll
        for (int kk = 0; kk < 32; ++kk) acc -= X[i][kk] * M[kk][32 + j];
        g_C[w*1024 + e] = acc;
    }
}

/* ------------- kernel B: warp-per-matrix one-sided Jacobi logm + transforms ------------- */
__global__ __launch_bounds__(WPB*32)
void logm_transform_kernel(const float* __restrict__ x) {
    __shared__ float Bsh[WPB][32][33];
    __shared__ float Ssh[WPB][32][33];
    __shared__ float Cs[3][32][33];
    __shared__ float wsh[WPB][32];

    const int tid  = threadIdx.x;
    const int wp   = tid >> 5;
    const int lane = tid & 31;
    const int mat  = blockIdx.x * WPB + wp;

    for (int e = tid; e < 3*1024; e += WPB*32) {
        int w = e >> 10, r = (e >> 5) & 31, cjj = e & 31;
        Cs[w][r][cjj] = g_C[e];
    }
    __syncthreads();

    const float* xin = x + (size_t)mat * 1024;
    float b[32];
    #pragma unroll
    for (int i = 0; i < 32; ++i) b[i] = xin[i*32 + lane];

    /* incremental column norm */
    float sn = 0.f;
    #pragma unroll
    for (int i = 0; i < 32; ++i) sn = fmaf(b[i], b[i], sn);

    float pb[32];
    for (int sw = 0; sw < NSWEEP; ++sw) {
        for (int r = 0; r < 31; ++r) {
            int partner;
            if (lane == 31) partner = r;
            else {
                partner = (2*r + 31 - lane) % 31;
                if (partner == lane) partner = 31;
            }

            float cross = 0.f;
            #pragma unroll
            for (int i = 0; i < 32; ++i) {
                pb[i] = __shfl_sync(0xffffffffu, b[i], partner);
                cross = fmaf(b[i], pb[i], cross);
            }
            float pn = __shfl_sync(0xffffffffu, sn, partner);

            bool isp = lane < partner;
            float delta = isp ? (pn - sn) : (sn - pn);

            float c = 1.f, s = 0.f;
            if (cross != 0.f) {
                float tau = delta / (2.f * cross);
                float tt  = copysignf(1.f, tau) / (fabsf(tau) + sqrtf(fmaf(tau, tau, 1.f)));
                c = rsqrtf(fmaf(tt, tt, 1.f));
                s = tt * c;
            }
            float ssgn = isp ? -s : s;
            #pragma unroll
            for (int i = 0; i < 32; ++i)
                b[i] = fmaf(c, b[i], ssgn * pb[i]);
            /* exact norm update: ||b'||^2 = c^2 sn + s^2 pn + 2 c ssgn cross */
            sn = fmaf(c*c, sn, fmaf(s*s, pn, 2.f*c*ssgn*cross));
        }
    }

    /* exact final norms (kills incremental drift) */
    sn = 0.f;
    #pragma unroll
    for (int i = 0; i < 32; ++i) sn = fmaf(b[i], b[i], sn);
    float lam = sqrtf(sn);
    float wgt = logf(lam) / sn;

    #pragma unroll
    for (int i = 0; i < 32; ++i) Bsh[wp][i][lane] = b[i];
    wsh[wp][lane] = wgt;
    __syncwarp();

    float rw[32];
    #pragma unroll
    for (int j = 0; j < 32; ++j) rw[j] = wsh[wp][j] * Bsh[wp][lane][j];
    #pragma unroll
    for (int k = 0; k < 32; ++k) {
        float acc = 0.f;
        #pragma unroll
        for (int j = 0; j < 32; ++j) acc = fmaf(rw[j], Bsh[wp][k][j], acc);
        Ssh[wp][lane][k] = (k == lane) ? 0.f : acc;
    }
    __syncwarp();

    #pragma unroll 1
    for (int wsel = 0; wsel < 3; ++wsel) {
        float crow[32];
        #pragma unroll
        for (int m = 0; m < 32; ++m) crow[m] = Cs[wsel][lane][m];

        float t[32];
        #pragma unroll
        for (int k = 0; k < 32; ++k) {
            float acc = 0.f;
            #pragma unroll
            for (int m = 0; m < 32; ++m) acc = fmaf(crow[m], Ssh[wp][m][k], acc);
            t[k] = acc;
        }

        float ss = 0.f;
        #pragma unroll
        for (int k = 0; k < 32; ++k) {
            float acc = 0.f;
            #pragma unroll
            for (int m = 0; m < 32; ++m) acc = fmaf(t[m], Cs[wsel][k][m], acc);
            if (k == lane) acc = 0.f;
            ss = fmaf(acc, acc, ss);
            Bsh[wp][lane][k] = acc;
        }
        __syncwarp();

        float* gout = (wsel == 0) ? g_qf : (wsel == 1) ? g_kf : g_vf;
        #pragma unroll
        for (int i = 0; i < 32; ++i)
            gout[(size_t)mat*1024 + i*32 + lane] = Bsh[wp][i][lane];

        if (wsel < 2) {
            #pragma unroll
            for (int off = 16; off; off >>= 1)
                ss += __shfl_down_sync(0xffffffffu, ss, off);
            if (lane == 0) ((wsel == 0) ? g_q2 : g_k2)[mat] = ss;
        }
        __syncwarp();
    }
}

/* ------------- kernel: zero D ------------- */
__global__ void zeroD_kernel() {
    int i = blockIdx.x * blockDim.x + threadIdx.x;
    if (i < NMAT) g_D[i] = 0.f;
}

/* ------------- kernel: rD = 1/D ------------- */
__global__ void rcpD_kernel() {
    int i = blockIdx.x * blockDim.x + threadIdx.x;
    if (i < NMAT) g_rD[i] = 1.f / g_D[i];
}

/* ------------- kernel C: 128x128 tile, 8x8/thread, k=16, double-buffered ------------- */
__global__ __launch_bounds__(256, 2)
void score_kernel() {
    const int b  = blockIdx.z;
    const int i0 = blockIdx.x * 128;
    const int j0 = blockIdx.y * 128;
    __shared__ float Ks[2][16][132];
    __shared__ float Qs[2][16][132];
    __shared__ float scol[128];
    const int tid = threadIdx.x;
    const int tx = tid & 15, ty = tid >> 4;
    const int lr = tid >> 1;
    const int lk = (tid & 1) * 4;

    float acc[8][8];
    #pragma unroll
    for (int m = 0; m < 8; ++m)
        #pragma unroll
        for (int n = 0; n < 8; ++n) acc[m][n] = 0.f;
    if (tid < 128) scol[tid] = 0.f;

    const float* kp = g_kf + ((size_t)(b*512 + j0 + lr))*1024 + lk;
    const float* qp = g_qf + ((size_t)(b*512 + i0 + lr))*1024 + lk;

    /* prologue: tile 0 -> buf 0 */
    float4 kv0 = *(const float4*)(kp);
    float4 kv1 = *(const float4*)(kp + 8);
    float4 qv0 = *(const float4*)(qp);
    float4 qv1 = *(const float4*)(qp + 8);
    Ks[0][lk+0][lr]=kv0.x; Ks[0][lk+1][lr]=kv0.y; Ks[0][lk+2][lr]=kv0.z; Ks[0][lk+3][lr]=kv0.w;
    Ks[0][lk+8][lr]=kv1.x; Ks[0][lk+9][lr]=kv1.y; Ks[0][lk+10][lr]=kv1.z; Ks[0][lk+11][lr]=kv1.w;
    Qs[0][lk+0][lr]=qv0.x; Qs[0][lk+1][lr]=qv0.y; Qs[0][lk+2][lr]=qv0.z; Qs[0][lk+3][lr]=qv0.w;
    Qs[0][lk+8][lr]=qv1.x; Qs[0][lk+9][lr]=qv1.y; Qs[0][lk+10][lr]=qv1.z; Qs[0][lk+11][lr]=qv1.w;
    __syncthreads();

    #pragma unroll 1
    for (int t = 0; t < 64; ++t) {
        const int cur = t & 1;
        if (t < 63) {
            const int k0 = (t + 1) * 16;
            kv0 = *(const float4*)(kp + k0);
            kv1 = *(const float4*)(kp + k0 + 8);
            qv0 = *(const float4*)(qp + k0);
            qv1 = *(const float4*)(qp + k0 + 8);
        }
        #pragma unroll
        for (int kk = 0; kk < 16; ++kk) {
            float4 a0 = *(const float4*)&Qs[cur][kk][tx*4];
            float4 a1 = *(const float4*)&Qs[cur][kk][tx*4 + 64];
            float4 b0 = *(const float4*)&Ks[cur][kk][ty*4];
            float4 b1 = *(const float4*)&Ks[cur][kk][ty*4 + 64];
            float av[8] = {a0.x,a0.y,a0.z,a0.w,a1.x,a1.y,a1.z,a1.w};
            float bv[8] = {b0.x,b0.y,b0.z,b0.w,b1.x,b1.y,b1.z,b1.w};
            #pragma unroll
            for (int m = 0; m < 8; ++m)
                #pragma unroll
                for (int n = 0; n < 8; ++n)
                    acc[m][n] = fmaf(bv[m], av[n], acc[m][n]);
        }
        if (t < 63) {
            const int nxt = cur ^ 1;
            Ks[nxt][lk+0][lr]=kv0.x; Ks[nxt][lk+1][lr]=kv0.y; Ks[nxt][lk+2][lr]=kv0.z; Ks[nxt][lk+3][lr]=kv0.w;
            Ks[nxt][lk+8][lr]=kv1.x; Ks[nxt][lk+9][lr]=kv1.y; Ks[nxt][lk+10][lr]=kv1.z; Ks[nxt][lk+11][lr]=kv1.w;
            Qs[nxt][lk+0][lr]=qv0.x; Qs[nxt][lk+1][lr]=qv0.y; Qs[nxt][lk+2][lr]=qv0.z; Qs[nxt][lk+3][lr]=qv0.w;
            Qs[nxt][lk+8][lr]=qv1.x; Qs[nxt][lk+9][lr]=qv1.y; Qs[nxt][lk+10][lr]=qv1.z; Qs[nxt][lk+11][lr]=qv1.w;
            __syncthreads();
        }
    }

    float q2c[8], k2r[8];
    #pragma unroll
    for (int n = 0; n < 8; ++n)
        q2c[n] = g_q2[b*512 + i0 + tx*4 + (n & 3) + (n >> 2)*64];
    #pragma unroll
    for (int m = 0; m < 8; ++m)
        k2r[m] = g_k2[b*512 + j0 + ty*4 + (m & 3) + (m >> 2)*64];

    float csum[8];
    #pragma unroll
    for (int n = 0; n < 8; ++n) csum[n] = 0.f;

    #pragma unroll
    for (int m = 0; m < 8; ++m) {
        int j = j0 + ty*4 + (m & 3) + (m >> 2)*64;
        float ev[8];
        #pragma unroll
        for (int n = 0; n < 8; ++n) {
            float d2 = k2r[m] + q2c[n] - 2.f * acc[m][n];
            d2 = fmaxf(d2, 1e-12f);
            float en = sqrtf(d2);
            float sc = 1.f / (1.f + __logf(1.f + en));
            ev[n] = __expf(sc);
            csum[n] += ev[n];
        }
        float* ep = g_E + ((size_t)b*512 + j)*512 + i0 + tx*4;
        float4 o0; o0.x = ev[0]; o0.y = ev[1]; o0.z = ev[2]; o0.w = ev[3];
        float4 o1; o1.x = ev[4]; o1.y = ev[5]; o1.z = ev[6]; o1.w = ev[7];
        *(float4*)ep = o0;
        *(float4*)(ep + 64) = o1;
    }

    #pragma unroll
    for (int n = 0; n < 8; ++n)
        atomicAdd(&scol[tx*4 + (n & 3) + (n >> 2)*64], csum[n]);
    __syncthreads();
    if (tid < 128) atomicAdd(&g_D[b*512 + i0 + tid], scol[tid]);
}

/* ------------- kernel D: out = E*diag(rD)*V, 128x128 tile, k=16, double-buffered ------------- */
__global__ __launch_bounds__(256, 2)
void out_kernel(float* __restrict__ out) {
    const int b  = blockIdx.z;
    const int c0 = blockIdx.x * 128;
    const int f0 = blockIdx.y * 128;
    __shared__ float As[2][16][132];   /* [a][c], E scaled by rD[a] */
    __shared__ float Bs[2][16][132];   /* [a][f] */
    const int tid = threadIdx.x;
    const int tx = tid & 15, ty = tid >> 4;
    const int lr = tid >> 1;
    const int lk = (tid & 1) * 4;
    const int la = tid >> 5;            /* 0..7 -> rows la, la+8 */
    const int lf = (tid & 31) * 4;

    float acc[8][8];
    #pragma unroll
    for (int m = 0; m < 8; ++m)
        #pragma unroll
        for (int n = 0; n < 8; ++n) acc[m][n] = 0.f;

    const float* ep  = g_E  + ((size_t)(b*512 + c0 + lr))*512 + lk;
    const float* vp  = g_vf + ((size_t)(b*512 + la))*1024 + f0 + lf;
    const float* rdp = g_rD + b*512 + lk;

    /* prologue: tile 0 -> buf 0 */
    float4 e0 = *(const float4*)(ep);
    float4 e1 = *(const float4*)(ep + 8);
    float4 r0 = *(const float4*)(rdp);
    float4 r1 = *(const float4*)(rdp + 8);
    float4 v0 = *(const float4*)(vp);
    float4 v1 = *(const float4*)(vp + (size_t)8*1024);
    As[0][lk+0][lr]=e0.x*r0.x; As[0][lk+1][lr]=e0.y*r0.y; As[0][lk+2][lr]=e0.z*r0.z; As[0][lk+3][lr]=e0.w*r0.w;
    As[0][lk+8][lr]=e1.x*r1.x; As[0][lk+9][lr]=e1.y*r1.y; As[0][lk+10][lr]=e1.z*r1.z; As[0][lk+11][lr]=e1.w*r1.w;
    *(float4*)&Bs[0][la][lf]     = v0;
    *(float4*)&Bs[0][la + 8][lf] = v1;
    __syncthreads();

    #pragma unroll 1
    for (int t = 0; t < 32; ++t) {
        const int cur = t & 1;
        if (t < 31) {
            const int a0 = (t + 1) * 16;
            e0 = *(const float4*)(ep + a0);
            e1 = *(const float4*)(ep + a0 + 8);
            r0 = *(const float4*)(rdp + a0);
            r1 = *(const float4*)(rdp + a0 + 8);
            v0 = *(const float4*)(vp + (size_t)a0*1024);
            v1 = *(const float4*)(vp + (size_t)(a0 + 8)*1024);
        }
        #pragma unroll
        for (int kk = 0; kk < 16; ++kk) {
            float4 c0v = *(const float4*)&As[cur][kk][ty*4];
            float4 c1v = *(const float4*)&As[cur][kk][ty*4 + 64];
            float4 f0v = *(const float4*)&Bs[cur][kk][tx*4];
            float4 f1v = *(const float4*)&Bs[cur][kk][tx*4 + 64];
            float cm[8] = {c0v.x,c0v.y,c0v.z,c0v.w,c1v.x,c1v.y,c1v.z,c1v.w};
            float fn[8] = {f0v.x,f0v.y,f0v.z,f0v.w,f1v.x,f1v.y,f1v.z,f1v.w};
            #pragma unroll
            for (int m = 0; m < 8; ++m)
                #pragma unroll
                for (int n = 0; n < 8; ++n)
                    acc[m][n] = fmaf(cm[m], fn[n], acc[m][n]);
        }
        if (t < 31) {
            const int nxt = cur ^ 1;
            As[nxt][lk+0][lr]=e0.x*r0.x; As[nxt][lk+1][lr]=e0.y*r0.y; As[nxt][lk+2][lr]=e0.z*r0.z; As[nxt][lk+3][lr]=e0.w*r0.w;
            As[nxt][lk+8][lr]=e1.x*r1.x; As[nxt][lk+9][lr]=e1.y*r1.y; As[nxt][lk+10][lr]=e1.z*r1.z; As[nxt][lk+11][lr]=e1.w*r1.w;
            *(float4*)&Bs[nxt][la][lf]     = v0;
            *(float4*)&Bs[nxt][la + 8][lf] = v1;
            __syncthreads();
        }
    }

    #pragma unroll
    for (int m = 0; m < 8; ++m) {
        int c = c0 + ty*4 + (m & 3) + (m >> 2)*64;
        float* op = out + ((size_t)(b*512 + c))*1024 + f0 + tx*4;
        float4 o0; o0.x = acc[m][0]; o0.y = acc[m][1]; o0.z = acc[m][2]; o0.w = acc[m][3];
        float4 o1; o1.x = acc[m][4]; o1.y = acc[m][5]; o1.z = acc[m][6]; o1.w = acc[m][7];
        *(float4*)op = o0;
        *(float4*)(op + 64) = o1;
    }
}

/* ------------- launch ------------- */
extern "C" void kernel_launch(void* const* d_in, const int* in_sizes, int n_in,
                              void* d_out, int out_size) {
    const float* x  = (const float*)d_in[0];
    const float* wq = (const float*)d_in[1];
    const float* wk = (const float*)d_in[2];
    const float* wv = (const float*)d_in[3];
    float* out = (float*)d_out;

    cayley_kernel<<<3, 64>>>(wq, wk, wv);
    logm_transform_kernel<<<NMAT/WPB, WPB*32>>>(x);
    zeroD_kernel<<<NMAT/256, 256>>>();
    score_kernel<<<dim3(4, 4, NB), 256>>>();
    rcpD_kernel<<<NMAT/256, 256>>>();
    out_kernel<<<dim3(4, 8, NB), 256>>>(out);
}

// round 8
// speedup vs baseline: 6.8200x; 1.0176x over previous
#include <cuda_runtime.h>
#include <math.h>

#define NB 16
#define NN 512
#define NMAT (NB*NN)   /* 8192 matrices */
#define NSWEEP 6
#define WPB 4          /* matrices (warps) per block in jacobi kernel */

/* ------------- device scratch (allocation-free) ------------- */
__device__ float g_C[3*1024];          /* Cayley matrices Cq,Ck,Cv */
__device__ float g_qf[(size_t)NMAT*1024];
__device__ float g_kf[(size_t)NMAT*1024];
__device__ float g_vf[(size_t)NMAT*1024];
__device__ float g_q2[NMAT];
__device__ float g_k2[NMAT];
__device__ float g_E[(size_t)NB*NN*NN];  /* exp(scores)[b][j][i] */
__device__ float g_D[NMAT];              /* col sums D[b*512+i]  */
__device__ float g_rD[NMAT];             /* 1/D */

/* ------------- kernel A: Cayley maps C = (I-X)(I+X)^-1, X = W - W^T ------------- */
__global__ void cayley_kernel(const float* __restrict__ Wq,
                              const float* __restrict__ Wk,
                              const float* __restrict__ Wv) {
    const int w = blockIdx.x;
    const float* W = (w == 0) ? Wq : (w == 1) ? Wk : Wv;
    __shared__ float M[32][64];
    __shared__ float X[32][32];
    __shared__ float fac[32];
    __shared__ float pivv;
    __shared__ int   pivi;
    const int t = threadIdx.x;    /* 64 threads */

    for (int e = t; e < 1024; e += 64) {
        int i = e >> 5, j = e & 31;
        float xv = W[i*32 + j] - W[j*32 + i];
        X[i][j] = xv;
        M[i][j]      = ((i == j) ? 1.f : 0.f) + xv;
        M[i][j + 32] = (i == j) ? 1.f : 0.f;
    }
    __syncthreads();

    for (int k = 0; k < 32; ++k) {
        if (t == 0) {
            float best = -1.f; int bi = k;
            for (int i = k; i < 32; ++i) {
                float v = fabsf(M[i][k]);
                if (v > best) { best = v; bi = i; }
            }
            pivi = bi;
        }
        __syncthreads();
        int pi = pivi;
        if (pi != k) { float tmp = M[k][t]; M[k][t] = M[pi][t]; M[pi][t] = tmp; }
        __syncthreads();
        if (t == 0) pivv = M[k][k];
        __syncthreads();
        float pv = pivv;
        M[k][t] /= pv;
        __syncthreads();
        if (t < 32) fac[t] = M[t][k];
        __syncthreads();
        for (int i = 0; i < 32; ++i)
            if (i != k) M[i][t] -= fac[i] * M[k][t];
        __syncthreads();
    }

    for (int e = t; e < 1024; e += 64) {
        int i = e >> 5, j = e & 31;
        float acc = M[i][32 + j];
        #pragma unroll
        for (int kk = 0; kk < 32; ++kk) acc -= X[i][kk] * M[kk][32 + j];
        g_C[w*1024 + e] = acc;
    }
}

/* ------------- kernel B: warp-per-matrix one-sided Jacobi logm + transforms ------------- */
__global__ __launch_bounds__(WPB*32)
void logm_transform_kernel(const float* __restrict__ x) {
    __shared__ float Bsh[WPB][32][33];
    __shared__ float Ssh[WPB][32][33];
    __shared__ float Cs[3][32][33];
    __shared__ float wsh[WPB][32];

    const int tid  = threadIdx.x;
    const int wp   = tid >> 5;
    const int lane = tid & 31;
    const int mat  = blockIdx.x * WPB + wp;

    for (int e = tid; e < 3*1024; e += WPB*32) {
        int w = e >> 10, r = (e >> 5) & 31, cjj = e & 31;
        Cs[w][r][cjj] = g_C[e];
    }
    __syncthreads();

    const float* xin = x + (size_t)mat * 1024;
    float b[32];
    #pragma unroll
    for (int i = 0; i < 32; ++i) b[i] = xin[i*32 + lane];

    /* incremental column norm */
    float sn = 0.f;
    #pragma unroll
    for (int i = 0; i < 32; ++i) sn = fmaf(b[i], b[i], sn);

    float pb[32];
    for (int sw = 0; sw < NSWEEP; ++sw) {
        int nrot = 0;
        for (int r = 0; r < 31; ++r) {
            int partner;
            if (lane == 31) partner = r;
            else {
                partner = (2*r + 31 - lane) % 31;
                if (partner == lane) partner = 31;
            }

            /* 4-way ILP cross dot product (order is index-sequential per chain;
               both lanes of a pair compute bitwise-identical cross) */
            float cr0 = 0.f, cr1 = 0.f, cr2 = 0.f, cr3 = 0.f;
            #pragma unroll
            for (int i = 0; i < 32; i += 4) {
                pb[i+0] = __shfl_sync(0xffffffffu, b[i+0], partner);
                pb[i+1] = __shfl_sync(0xffffffffu, b[i+1], partner);
                pb[i+2] = __shfl_sync(0xffffffffu, b[i+2], partner);
                pb[i+3] = __shfl_sync(0xffffffffu, b[i+3], partner);
                cr0 = fmaf(b[i+0], pb[i+0], cr0);
                cr1 = fmaf(b[i+1], pb[i+1], cr1);
                cr2 = fmaf(b[i+2], pb[i+2], cr2);
                cr3 = fmaf(b[i+3], pb[i+3], cr3);
            }
            float cross = (cr0 + cr1) + (cr2 + cr3);
            float pn = __shfl_sync(0xffffffffu, sn, partner);

            /* converged pair: rotation angle < ~1e-7 -> numerically a no-op */
            bool doRot = (cross*cross > 1e-14f * sn * pn);
            if (__any_sync(0xffffffffu, doRot)) {
                ++nrot;
                bool isp = lane < partner;
                float delta = isp ? (pn - sn) : (sn - pn);

                float c = 1.f, s = 0.f;
                if (cross != 0.f) {
                    float tau = delta / (2.f * cross);
                    float tt  = copysignf(1.f, tau) / (fabsf(tau) + sqrtf(fmaf(tau, tau, 1.f)));
                    c = rsqrtf(fmaf(tt, tt, 1.f));
                    s = tt * c;
                }
                float ssgn = isp ? -s : s;
                #pragma unroll
                for (int i = 0; i < 32; ++i)
                    b[i] = fmaf(c, b[i], ssgn * pb[i]);
                /* exact norm update: ||b'||^2 = c^2 sn + s^2 pn + 2 c ssgn cross */
                sn = fmaf(c*c, sn, fmaf(s*s, pn, 2.f*c*ssgn*cross));
            }
        }
        if (nrot == 0) break;   /* warp-uniform: whole sweep was identity */
    }

    /* exact final norms (kills incremental drift) */
    sn = 0.f;
    #pragma unroll
    for (int i = 0; i < 32; ++i) sn = fmaf(b[i], b[i], sn);
    float lam = sqrtf(sn);
    float wgt = logf(lam) / sn;

    #pragma unroll
    for (int i = 0; i < 32; ++i) Bsh[wp][i][lane] = b[i];
    wsh[wp][lane] = wgt;
    __syncwarp();

    float rw[32];
    #pragma unroll
    for (int j = 0; j < 32; ++j) rw[j] = wsh[wp][j] * Bsh[wp][lane][j];
    #pragma unroll
    for (int k = 0; k < 32; ++k) {
        float acc = 0.f;
        #pragma unroll
        for (int j = 0; j < 32; ++j) acc = fmaf(rw[j], Bsh[wp][k][j], acc);
        Ssh[wp][lane][k] = (k == lane) ? 0.f : acc;
    }
    __syncwarp();

    #pragma unroll 1
    for (int wsel = 0; wsel < 3; ++wsel) {
        float crow[32];
        #pragma unroll
        for (int m = 0; m < 32; ++m) crow[m] = Cs[wsel][lane][m];

        float t[32];
        #pragma unroll
        for (int k = 0; k < 32; ++k) {
            float acc = 0.f;
            #pragma unroll
            for (int m = 0; m < 32; ++m) acc = fmaf(crow[m], Ssh[wp][m][k], acc);
            t[k] = acc;
        }

        float ss = 0.f;
        #pragma unroll
        for (int k = 0; k < 32; ++k) {
            float acc = 0.f;
            #pragma unroll
            for (int m = 0; m < 32; ++m) acc = fmaf(t[m], Cs[wsel][k][m], acc);
            if (k == lane) acc = 0.f;
            ss = fmaf(acc, acc, ss);
            Bsh[wp][lane][k] = acc;
        }
        __syncwarp();

        float* gout = (wsel == 0) ? g_qf : (wsel == 1) ? g_kf : g_vf;
        #pragma unroll
        for (int i = 0; i < 32; ++i)
            gout[(size_t)mat*1024 + i*32 + lane] = Bsh[wp][i][lane];

        if (wsel < 2) {
            #pragma unroll
            for (int off = 16; off; off >>= 1)
                ss += __shfl_down_sync(0xffffffffu, ss, off);
            if (lane == 0) ((wsel == 0) ? g_q2 : g_k2)[mat] = ss;
        }
        __syncwarp();
    }
}

/* ------------- kernel: zero D ------------- */
__global__ void zeroD_kernel() {
    int i = blockIdx.x * blockDim.x + threadIdx.x;
    if (i < NMAT) g_D[i] = 0.f;
}

/* ------------- kernel: rD = 1/D ------------- */
__global__ void rcpD_kernel() {
    int i = blockIdx.x * blockDim.x + threadIdx.x;
    if (i < NMAT) g_rD[i] = 1.f / g_D[i];
}

/* ------------- kernel C: 128x128 tile, 8x8/thread, k=16, double-buffered ------------- */
__global__ __launch_bounds__(256, 2)
void score_kernel() {
    const int b  = blockIdx.z;
    const int i0 = blockIdx.x * 128;
    const int j0 = blockIdx.y * 128;
    __shared__ float Ks[2][16][132];
    __shared__ float Qs[2][16][132];
    __shared__ float scol[128];
    const int tid = threadIdx.x;
    const int tx = tid & 15, ty = tid >> 4;
    const int lr = tid >> 1;
    const int lk = (tid & 1) * 4;

    float acc[8][8];
    #pragma unroll
    for (int m = 0; m < 8; ++m)
        #pragma unroll
        for (int n = 0; n < 8; ++n) acc[m][n] = 0.f;
    if (tid < 128) scol[tid] = 0.f;

    const float* kp = g_kf + ((size_t)(b*512 + j0 + lr))*1024 + lk;
    const float* qp = g_qf + ((size_t)(b*512 + i0 + lr))*1024 + lk;

    /* prologue: tile 0 -> buf 0 */
    float4 kv0 = *(const float4*)(kp);
    float4 kv1 = *(const float4*)(kp + 8);
    float4 qv0 = *(const float4*)(qp);
    float4 qv1 = *(const float4*)(qp + 8);
    Ks[0][lk+0][lr]=kv0.x; Ks[0][lk+1][lr]=kv0.y; Ks[0][lk+2][lr]=kv0.z; Ks[0][lk+3][lr]=kv0.w;
    Ks[0][lk+8][lr]=kv1.x; Ks[0][lk+9][lr]=kv1.y; Ks[0][lk+10][lr]=kv1.z; Ks[0][lk+11][lr]=kv1.w;
    Qs[0][lk+0][lr]=qv0.x; Qs[0][lk+1][lr]=qv0.y; Qs[0][lk+2][lr]=qv0.z; Qs[0][lk+3][lr]=qv0.w;
    Qs[0][lk+8][lr]=qv1.x; Qs[0][lk+9][lr]=qv1.y; Qs[0][lk+10][lr]=qv1.z; Qs[0][lk+11][lr]=qv1.w;
    __syncthreads();

    #pragma unroll 1
    for (int t = 0; t < 64; ++t) {
        const int cur = t & 1;
        if (t < 63) {
            const int k0 = (t + 1) * 16;
            kv0 = *(const float4*)(kp + k0);
            kv1 = *(const float4*)(kp + k0 + 8);
            qv0 = *(const float4*)(qp + k0);
            qv1 = *(const float4*)(qp + k0 + 8);
        }
        #pragma unroll
        for (int kk = 0; kk < 16; ++kk) {
            float4 a0 = *(const float4*)&Qs[cur][kk][tx*4];
            float4 a1 = *(const float4*)&Qs[cur][kk][tx*4 + 64];
            float4 b0 = *(const float4*)&Ks[cur][kk][ty*4];
            float4 b1 = *(const float4*)&Ks[cur][kk][ty*4 + 64];
            float av[8] = {a0.x,a0.y,a0.z,a0.w,a1.x,a1.y,a1.z,a1.w};
            float bv[8] = {b0.x,b0.y,b0.z,b0.w,b1.x,b1.y,b1.z,b1.w};
            #pragma unroll
            for (int m = 0; m < 8; ++m)
                #pragma unroll
                for (int n = 0; n < 8; ++n)
                    acc[m][n] = fmaf(bv[m], av[n], acc[m][n]);
        }
        if (t < 63) {
            const int nxt = cur ^ 1;
            Ks[nxt][lk+0][lr]=kv0.x; Ks[nxt][lk+1][lr]=kv0.y; Ks[nxt][lk+2][lr]=kv0.z; Ks[nxt][lk+3][lr]=kv0.w;
            Ks[nxt][lk+8][lr]=kv1.x; Ks[nxt][lk+9][lr]=kv1.y; Ks[nxt][lk+10][lr]=kv1.z; Ks[nxt][lk+11][lr]=kv1.w;
            Qs[nxt][lk+0][lr]=qv0.x; Qs[nxt][lk+1][lr]=qv0.y; Qs[nxt][lk+2][lr]=qv0.z; Qs[nxt][lk+3][lr]=qv0.w;
            Qs[nxt][lk+8][lr]=qv1.x; Qs[nxt][lk+9][lr]=qv1.y; Qs[nxt][lk+10][lr]=qv1.z; Qs[nxt][lk+11][lr]=qv1.w;
            __syncthreads();
        }
    }

    float q2c[8], k2r[8];
    #pragma unroll
    for (int n = 0; n < 8; ++n)
        q2c[n] = g_q2[b*512 + i0 + tx*4 + (n & 3) + (n >> 2)*64];
    #pragma unroll
    for (int m = 0; m < 8; ++m)
        k2r[m] = g_k2[b*512 + j0 + ty*4 + (m & 3) + (m >> 2)*64];

    float csum[8];
    #pragma unroll
    for (int n = 0; n < 8; ++n) csum[n] = 0.f;

    #pragma unroll
    for (int m = 0; m < 8; ++m) {
        int j = j0 + ty*4 + (m & 3) + (m >> 2)*64;
        float ev[8];
        #pragma unroll
        for (int n = 0; n < 8; ++n) {
            float d2 = k2r[m] + q2c[n] - 2.f * acc[m][n];
            d2 = fmaxf(d2, 1e-12f);
            float en = sqrtf(d2);
            float sc = 1.f / (1.f + __logf(1.f + en));
            ev[n] = __expf(sc);
            csum[n] += ev[n];
        }
        float* ep = g_E + ((size_t)b*512 + j)*512 + i0 + tx*4;
        float4 o0; o0.x = ev[0]; o0.y = ev[1]; o0.z = ev[2]; o0.w = ev[3];
        float4 o1; o1.x = ev[4]; o1.y = ev[5]; o1.z = ev[6]; o1.w = ev[7];
        *(float4*)ep = o0;
        *(float4*)(ep + 64) = o1;
    }

    #pragma unroll
    for (int n = 0; n < 8; ++n)
        atomicAdd(&scol[tx*4 + (n & 3) + (n >> 2)*64], csum[n]);
    __syncthreads();
    if (tid < 128) atomicAdd(&g_D[b*512 + i0 + tid], scol[tid]);
}

/* ------------- kernel D: out = E*diag(rD)*V, 128x128 tile, k=16, double-buffered ------------- */
__global__ __launch_bounds__(256, 2)
void out_kernel(float* __restrict__ out) {
    const int b  = blockIdx.z;
    const int c0 = blockIdx.x * 128;
    const int f0 = blockIdx.y * 128;
    __shared__ float As[2][16][132];   /* [a][c], E scaled by rD[a] */
    __shared__ float Bs[2][16][132];   /* [a][f] */
    const int tid = threadIdx.x;
    const int tx = tid & 15, ty = tid >> 4;
    const int lr = tid >> 1;
    const int lk = (tid & 1) * 4;
    const int la = tid >> 5;            /* 0..7 -> rows la, la+8 */
    const int lf = (tid & 31) * 4;

    float acc[8][8];
    #pragma unroll
    for (int m = 0; m < 8; ++m)
        #pragma unroll
        for (int n = 0; n < 8; ++n) acc[m][n] = 0.f;

    const float* ep  = g_E  + ((size_t)(b*512 + c0 + lr))*512 + lk;
    const float* vp  = g_vf + ((size_t)(b*512 + la))*1024 + f0 + lf;
    const float* rdp = g_rD + b*512 + lk;

    /* prologue: tile 0 -> buf 0 */
    float4 e0 = *(const float4*)(ep);
    float4 e1 = *(const float4*)(ep + 8);
    float4 r0 = *(const float4*)(rdp);
    float4 r1 = *(const float4*)(rdp + 8);
    float4 v0 = *(const float4*)(vp);
    float4 v1 = *(const float4*)(vp + (size_t)8*1024);
    As[0][lk+0][lr]=e0.x*r0.x; As[0][lk+1][lr]=e0.y*r0.y; As[0][lk+2][lr]=e0.z*r0.z; As[0][lk+3][lr]=e0.w*r0.w;
    As[0][lk+8][lr]=e1.x*r1.x; As[0][lk+9][lr]=e1.y*r1.y; As[0][lk+10][lr]=e1.z*r1.z; As[0][lk+11][lr]=e1.w*r1.w;
    *(float4*)&Bs[0][la][lf]     = v0;
    *(float4*)&Bs[0][la + 8][lf] = v1;
    __syncthreads();

    #pragma unroll 1
    for (int t = 0; t < 32; ++t) {
        const int cur = t & 1;
        if (t < 31) {
            const int a0 = (t + 1) * 16;
            e0 = *(const float4*)(ep + a0);
            e1 = *(const float4*)(ep + a0 + 8);
            r0 = *(const float4*)(rdp + a0);
            r1 = *(const float4*)(rdp + a0 + 8);
            v0 = *(const float4*)(vp + (size_t)a0*1024);
            v1 = *(const float4*)(vp + (size_t)(a0 + 8)*1024);
        }
        #pragma unroll
        for (int kk = 0; kk < 16; ++kk) {
            float4 c0v = *(const float4*)&As[cur][kk][ty*4];
            float4 c1v = *(const float4*)&As[cur][kk][ty*4 + 64];
            float4 f0v = *(const float4*)&Bs[cur][kk][tx*4];
            float4 f1v = *(const float4*)&Bs[cur][kk][tx*4 + 64];
            float cm[8] = {c0v.x,c0v.y,c0v.z,c0v.w,c1v.x,c1v.y,c1v.z,c1v.w};
            float fn[8] = {f0v.x,f0v.y,f0v.z,f0v.w,f1v.x,f1v.y,f1v.z,f1v.w};
            #pragma unroll
            for (int m = 0; m < 8; ++m)
                #pragma unroll
                for (int n = 0; n < 8; ++n)
                    acc[m][n] = fmaf(cm[m], fn[n], acc[m][n]);
        }
        if (t < 31) {
            const int nxt = cur ^ 1;
            As[nxt][lk+0][lr]=e0.x*r0.x; As[nxt][lk+1][lr]=e0.y*r0.y; As[nxt][lk+2][lr]=e0.z*r0.z; As[nxt][lk+3][lr]=e0.w*r0.w;
            As[nxt][lk+8][lr]=e1.x*r1.x; As[nxt][lk+9][lr]=e1.y*r1.y; As[nxt][lk+10][lr]=e1.z*r1.z; As[nxt][lk+11][lr]=e1.w*r1.w;
            *(float4*)&Bs[nxt][la][lf]     = v0;
            *(float4*)&Bs[nxt][la + 8][lf] = v1;
            __syncthreads();
        }
    }

    #pragma unroll
    for (int m = 0; m < 8; ++m) {
        int c = c0 + ty*4 + (m & 3) + (m >> 2)*64;
        float* op = out + ((size_t)(b*512 + c))*1024 + f0 + tx*4;
        float4 o0; o0.x = acc[m][0]; o0.y = acc[m][1]; o0.z = acc[m][2]; o0.w = acc[m][3];
        float4 o1; o1.x = acc[m][4]; o1.y = acc[m][5]; o1.z = acc[m][6]; o1.w = acc[m][7];
        *(float4*)op = o0;
        *(float4*)(op + 64) = o1;
    }
}

/* ------------- launch ------------- */
extern "C" void kernel_launch(void* const* d_in, const int* in_sizes, int n_in,
                              void* d_out, int out_size) {
    const float* x  = (const float*)d_in[0];
    const float* wq = (const float*)d_in[1];
    const float* wk = (const float*)d_in[2];
    const float* wv = (const float*)d_in[3];
    float* out = (float*)d_out;

    cayley_kernel<<<3, 64>>>(wq, wk, wv);
    logm_transform_kernel<<<NMAT/WPB, WPB*32>>>(x);
    zeroD_kernel<<<NMAT/256, 256>>>();
    score_kernel<<<dim3(4, 4, NB), 256>>>();
    rcpD_kernel<<<NMAT/256, 256>>>();
    out_kernel<<<dim3(4, 8, NB), 256>>>(out);
}

// round 10
// speedup vs baseline: 7.6488x; 1.1215x over previous
#include <cuda_runtime.h>
#include <math.h>

#define NB 16
#define NN 512
#define NMAT (NB*NN)   /* 8192 matrices */
#define NSWEEP 6
#define WPB 4          /* matrices (warps) per block in jacobi kernel */
#define NPK 512        /* packed (lower-tri) stride: 496 used + 16 pad */
#define NTRI 496       /* strict lower triangle of 32x32 */

/* ------------- device scratch (allocation-free) ------------- */
__device__ float g_C[3*1024];            /* Cayley matrices Cq,Ck,Cv */
__device__ float g_qf[(size_t)NMAT*NPK]; /* packed sqrt(2)*lower(q) */
__device__ float g_kf[(size_t)NMAT*NPK]; /* packed sqrt(2)*lower(k) */
__device__ float g_vf[(size_t)NMAT*NPK]; /* packed lower(v)         */
__device__ float g_q2[NMAT];
__device__ float g_k2[NMAT];
__device__ float g_E[(size_t)NB*NN*NN];  /* exp(scores)[b][j][i] */
__device__ float g_D[NMAT];              /* col sums D[b*512+i]  */
__device__ float g_rD[NMAT];             /* 1/D */
__device__ int2  g_lut[NTRI];            /* t -> (i,j), i>j */

/* ------------- LUT init: t -> (i,j) strict lower triangle ------------- */
__global__ void lut_kernel() {
    int t = blockIdx.x * blockDim.x + threadIdx.x;
    if (t >= NTRI) return;
    int i = (int)((1.0 + sqrt(1.0 + 8.0*(double)t)) * 0.5);
    while (i*(i-1)/2 > t) --i;
    while ((i+1)*i/2 <= t) ++i;
    int j = t - i*(i-1)/2;
    g_lut[t] = make_int2(i, j);
}

/* ------------- kernel A: Cayley maps C = (I-X)(I+X)^-1, X = W - W^T ------------- */
__global__ void cayley_kernel(const float* __restrict__ Wq,
                              const float* __restrict__ Wk,
                              const float* __restrict__ Wv) {
    const int w = blockIdx.x;
    const float* W = (w == 0) ? Wq : (w == 1) ? Wk : Wv;
    __shared__ float M[32][64];
    __shared__ float X[32][32];
    __shared__ float fac[32];
    __shared__ float pivv;
    __shared__ int   pivi;
    const int t = threadIdx.x;    /* 64 threads */

    for (int e = t; e < 1024; e += 64) {
        int i = e >> 5, j = e & 31;
        float xv = W[i*32 + j] - W[j*32 + i];
        X[i][j] = xv;
        M[i][j]      = ((i == j) ? 1.f : 0.f) + xv;
        M[i][j + 32] = (i == j) ? 1.f : 0.f;
    }
    __syncthreads();

    for (int k = 0; k < 32; ++k) {
        if (t == 0) {
            float best = -1.f; int bi = k;
            for (int i = k; i < 32; ++i) {
                float v = fabsf(M[i][k]);
                if (v > best) { best = v; bi = i; }
            }
            pivi = bi;
        }
        __syncthreads();
        int pi = pivi;
        if (pi != k) { float tmp = M[k][t]; M[k][t] = M[pi][t]; M[pi][t] = tmp; }
        __syncthreads();
        if (t == 0) pivv = M[k][k];
        __syncthreads();
        float pv = pivv;
        M[k][t] /= pv;
        __syncthreads();
        if (t < 32) fac[t] = M[t][k];
        __syncthreads();
        for (int i = 0; i < 32; ++i)
            if (i != k) M[i][t] -= fac[i] * M[k][t];
        __syncthreads();
    }

    for (int e = t; e < 1024; e += 64) {
        int i = e >> 5, j = e & 31;
        float acc = M[i][32 + j];
        #pragma unroll
        for (int kk = 0; kk < 32; ++kk) acc -= X[i][kk] * M[kk][32 + j];
        g_C[w*1024 + e] = acc;
    }
}

/* ------------- kernel B: warp-per-matrix one-sided Jacobi logm + transforms ------------- */
__global__ __launch_bounds__(WPB*32)
void logm_transform_kernel(const float* __restrict__ x) {
    __shared__ float Bsh[WPB][32][33];
    __shared__ float Ssh[WPB][32][33];
    __shared__ float Cs[3][32][33];
    __shared__ float wsh[WPB][32];

    const int tid  = threadIdx.x;
    const int wp   = tid >> 5;
    const int lane = tid & 31;
    const int mat  = blockIdx.x * WPB + wp;

    for (int e = tid; e < 3*1024; e += WPB*32) {
        int w = e >> 10, r = (e >> 5) & 31, cjj = e & 31;
        Cs[w][r][cjj] = g_C[e];
    }
    __syncthreads();

    const float* xin = x + (size_t)mat * 1024;
    float b[32];
    #pragma unroll
    for (int i = 0; i < 32; ++i) b[i] = xin[i*32 + lane];

    float sn = 0.f;
    #pragma unroll
    for (int i = 0; i < 32; ++i) sn = fmaf(b[i], b[i], sn);

    float pb[32];
    for (int sw = 0; sw < NSWEEP; ++sw) {
        int nrot = 0;
        for (int r = 0; r < 31; ++r) {
            int partner;
            if (lane == 31) partner = r;
            else {
                partner = (2*r + 31 - lane) % 31;
                if (partner == lane) partner = 31;
            }

            float cr0 = 0.f, cr1 = 0.f, cr2 = 0.f, cr3 = 0.f;
            #pragma unroll
            for (int i = 0; i < 32; i += 4) {
                pb[i+0] = __shfl_sync(0xffffffffu, b[i+0], partner);
                pb[i+1] = __shfl_sync(0xffffffffu, b[i+1], partner);
                pb[i+2] = __shfl_sync(0xffffffffu, b[i+2], partner);
                pb[i+3] = __shfl_sync(0xffffffffu, b[i+3], partner);
                cr0 = fmaf(b[i+0], pb[i+0], cr0);
                cr1 = fmaf(b[i+1], pb[i+1], cr1);
                cr2 = fmaf(b[i+2], pb[i+2], cr2);
                cr3 = fmaf(b[i+3], pb[i+3], cr3);
            }
            float cross = (cr0 + cr1) + (cr2 + cr3);
            float pn = __shfl_sync(0xffffffffu, sn, partner);

            bool doRot = (cross*cross > 1e-10f * sn * pn);
            if (__any_sync(0xffffffffu, doRot)) {
                ++nrot;
                bool isp = lane < partner;
                float delta = isp ? (pn - sn) : (sn - pn);

                float c = 1.f, s = 0.f;
                if (cross != 0.f) {
                    float tau = delta / (2.f * cross);
                    float tt  = copysignf(1.f, tau) / (fabsf(tau) + sqrtf(fmaf(tau, tau, 1.f)));
                    c = rsqrtf(fmaf(tt, tt, 1.f));
                    s = tt * c;
                }
                float ssgn = isp ? -s : s;
                #pragma unroll
                for (int i = 0; i < 32; ++i)
                    b[i] = fmaf(c, b[i], ssgn * pb[i]);
                sn = fmaf(c*c, sn, fmaf(s*s, pn, 2.f*c*ssgn*cross));
            }
        }
        if (nrot == 0) break;
    }

    /* exact final norms */
    sn = 0.f;
    #pragma unroll
    for (int i = 0; i < 32; ++i) sn = fmaf(b[i], b[i], sn);
    float lam = sqrtf(sn);
    float wgt = logf(lam) / sn;

    #pragma unroll
    for (int i = 0; i < 32; ++i) Bsh[wp][i][lane] = b[i];
    wsh[wp][lane] = wgt;
    __syncwarp();

    float rw[32];
    #pragma unroll
    for (int j = 0; j < 32; ++j) rw[j] = wsh[wp][j] * Bsh[wp][lane][j];
    #pragma unroll
    for (int k = 0; k < 32; ++k) {
        float acc = 0.f;
        #pragma unroll
        for (int j = 0; j < 32; ++j) acc = fmaf(rw[j], Bsh[wp][k][j], acc);
        Ssh[wp][lane][k] = (k == lane) ? 0.f : acc;
    }
    __syncwarp();

    #pragma unroll 1
    for (int wsel = 0; wsel < 3; ++wsel) {
        float crow[32];
        #pragma unroll
        for (int m = 0; m < 32; ++m) crow[m] = Cs[wsel][lane][m];

        float t[32];
        #pragma unroll
        for (int k = 0; k < 32; ++k) {
            float acc = 0.f;
            #pragma unroll
            for (int m = 0; m < 32; ++m) acc = fmaf(crow[m], Ssh[wp][m][k], acc);
            t[k] = acc;
        }

        float ss = 0.f;
        #pragma unroll
        for (int k = 0; k < 32; ++k) {
            float acc = 0.f;
            #pragma unroll
            for (int m = 0; m < 32; ++m) acc = fmaf(t[m], Cs[wsel][k][m], acc);
            if (k == lane) acc = 0.f;
            ss = fmaf(acc, acc, ss);
            Bsh[wp][lane][k] = acc;       /* full symmetric Y staged in shared */
        }
        __syncwarp();

        /* packed write: strict lower triangle, sqrt(2)-scaled for q/k */
        float* gout = (wsel == 0) ? g_qf : (wsel == 1) ? g_kf : g_vf;
        const float scale = (wsel < 2) ? 1.41421356237309515f : 1.f;
        #pragma unroll
        for (int t2 = lane; t2 < NPK; t2 += 32) {
            float val = 0.f;
            if (t2 < NTRI) {
                int2 ij = g_lut[t2];
                val = scale * Bsh[wp][ij.x][ij.y];
            }
            gout[(size_t)mat*NPK + t2] = val;
        }

        if (wsel < 2) {
            #pragma unroll
            for (int off = 16; off; off >>= 1)
                ss += __shfl_down_sync(0xffffffffu, ss, off);
            if (lane == 0) ((wsel == 0) ? g_q2 : g_k2)[mat] = ss;
        }
        __syncwarp();
    }
}

/* ------------- kernel: zero D ------------- */
__global__ void zeroD_kernel() {
    int i = blockIdx.x * blockDim.x + threadIdx.x;
    if (i < NMAT) g_D[i] = 0.f;
}

/* ------------- kernel: rD = 1/D ------------- */
__global__ void rcpD_kernel() {
    int i = blockIdx.x * blockDim.x + threadIdx.x;
    if (i < NMAT) g_rD[i] = 1.f / g_D[i];
}

/* ------------- kernel: zero diagonal of output ------------- */
__global__ void zeroDiag_kernel(float* __restrict__ out) {
    int t = blockIdx.x * blockDim.x + threadIdx.x;   /* NMAT*32 threads */
    int m = t >> 5, d = t & 31;
    out[(size_t)m*1024 + d*33] = 0.f;
}

/* ------------- kernel C: 128x128 tile, 8x8/thread, packed K=512, double-buffered ------------- */
__global__ __launch_bounds__(256, 2)
void score_kernel() {
    const int b  = blockIdx.z;
    const int i0 = blockIdx.x * 128;
    const int j0 = blockIdx.y * 128;
    __shared__ float Ks[2][16][132];
    __shared__ float Qs[2][16][132];
    __shared__ float scol[128];
    const int tid = threadIdx.x;
    const int tx = tid & 15, ty = tid >> 4;
    const int lr = tid >> 1;
    const int lk = (tid & 1) * 4;

    float acc[8][8];
    #pragma unroll
    for (int m = 0; m < 8; ++m)
        #pragma unroll
        for (int n = 0; n < 8; ++n) acc[m][n] = 0.f;
    if (tid < 128) scol[tid] = 0.f;

    const float* kp = g_kf + ((size_t)(b*512 + j0 + lr))*NPK + lk;
    const float* qp = g_qf + ((size_t)(b*512 + i0 + lr))*NPK + lk;

    float4 kv0 = *(const float4*)(kp);
    float4 kv1 = *(const float4*)(kp + 8);
    float4 qv0 = *(const float4*)(qp);
    float4 qv1 = *(const float4*)(qp + 8);
    Ks[0][lk+0][lr]=kv0.x; Ks[0][lk+1][lr]=kv0.y; Ks[0][lk+2][lr]=kv0.z; Ks[0][lk+3][lr]=kv0.w;
    Ks[0][lk+8][lr]=kv1.x; Ks[0][lk+9][lr]=kv1.y; Ks[0][lk+10][lr]=kv1.z; Ks[0][lk+11][lr]=kv1.w;
    Qs[0][lk+0][lr]=qv0.x; Qs[0][lk+1][lr]=qv0.y; Qs[0][lk+2][lr]=qv0.z; Qs[0][lk+3][lr]=qv0.w;
    Qs[0][lk+8][lr]=qv1.x; Qs[0][lk+9][lr]=qv1.y; Qs[0][lk+10][lr]=qv1.z; Qs[0][lk+11][lr]=qv1.w;
    __syncthreads();

    #pragma unroll 1
    for (int t = 0; t < 32; ++t) {
        const int cur = t & 1;
        if (t < 31) {
            const int k0 = (t + 1) * 16;
            kv0 = *(const float4*)(kp + k0);
            kv1 = *(const float4*)(kp + k0 + 8);
            qv0 = *(const float4*)(qp + k0);
            qv1 = *(const float4*)(qp + k0 + 8);
        }
        #pragma unroll
        for (int kk = 0; kk < 16; ++kk) {
            float4 a0 = *(const float4*)&Qs[cur][kk][tx*4];
            float4 a1 = *(const float4*)&Qs[cur][kk][tx*4 + 64];
            float4 b0 = *(const float4*)&Ks[cur][kk][ty*4];
            float4 b1 = *(const float4*)&Ks[cur][kk][ty*4 + 64];
            float av[8] = {a0.x,a0.y,a0.z,a0.w,a1.x,a1.y,a1.z,a1.w};
            float bv[8] = {b0.x,b0.y,b0.z,b0.w,b1.x,b1.y,b1.z,b1.w};
            #pragma unroll
            for (int m = 0; m < 8; ++m)
                #pragma unroll
                for (int n = 0; n < 8; ++n)
                    acc[m][n] = fmaf(bv[m], av[n], acc[m][n]);
        }
        if (t < 31) {
            const int nxt = cur ^ 1;
            Ks[nxt][lk+0][lr]=kv0.x; Ks[nxt][lk+1][lr]=kv0.y; Ks[nxt][lk+2][lr]=kv0.z; Ks[nxt][lk+3][lr]=kv0.w;
            Ks[nxt][lk+8][lr]=kv1.x; Ks[nxt][lk+9][lr]=kv1.y; Ks[nxt][lk+10][lr]=kv1.z; Ks[nxt][lk+11][lr]=kv1.w;
            Qs[nxt][lk+0][lr]=qv0.x; Qs[nxt][lk+1][lr]=qv0.y; Qs[nxt][lk+2][lr]=qv0.z; Qs[nxt][lk+3][lr]=qv0.w;
            Qs[nxt][lk+8][lr]=qv1.x; Qs[nxt][lk+9][lr]=qv1.y; Qs[nxt][lk+10][lr]=qv1.z; Qs[nxt][lk+11][lr]=qv1.w;
            __syncthreads();
        }
    }

    float q2c[8], k2r[8];
    #pragma unroll
    for (int n = 0; n < 8; ++n)
        q2c[n] = g_q2[b*512 + i0 + tx*4 + (n & 3) + (n >> 2)*64];
    #pragma unroll
    for (int m = 0; m < 8; ++m)
        k2r[m] = g_k2[b*512 + j0 + ty*4 + (m & 3) + (m >> 2)*64];

    float csum[8];
    #pragma unroll
    for (int n = 0; n < 8; ++n) csum[n] = 0.f;

    #pragma unroll
    for (int m = 0; m < 8; ++m) {
        int j = j0 + ty*4 + (m & 3) + (m >> 2)*64;
        float ev[8];
        #pragma unroll
        for (int n = 0; n < 8; ++n) {
            float d2 = k2r[m] + q2c[n] - 2.f * acc[m][n];
            d2 = fmaxf(d2, 1e-12f);
            float en = sqrtf(d2);
            float sc = 1.f / (1.f + __logf(1.f + en));
            ev[n] = __expf(sc);
            csum[n] += ev[n];
        }
        float* ep = g_E + ((size_t)b*512 + j)*512 + i0 + tx*4;
        float4 o0; o0.x = ev[0]; o0.y = ev[1]; o0.z = ev[2]; o0.w = ev[3];
        float4 o1; o1.x = ev[4]; o1.y = ev[5]; o1.z = ev[6]; o1.w = ev[7];
        *(float4*)ep = o0;
        *(float4*)(ep + 64) = o1;
    }

    #pragma unroll
    for (int n = 0; n < 8; ++n)
        atomicAdd(&scol[tx*4 + (n & 3) + (n >> 2)*64], csum[n]);
    __syncthreads();
    if (tid < 128) atomicAdd(&g_D[b*512 + i0 + tid], scol[tid]);
}

/* ------------- kernel D: out = E*diag(rD)*Vpacked, mirrored epilogue ------------- */
__global__ __launch_bounds__(256, 2)
void out_kernel(float* __restrict__ out) {
    const int b  = blockIdx.z;
    const int c0 = blockIdx.x * 128;
    const int f0 = blockIdx.y * 128;     /* packed f-tile: 0,128,256,384 */
    __shared__ float As[2][16][132];     /* [a][c], E scaled by rD[a] */
    __shared__ float Bs[2][16][132];     /* [a][fpacked] */
    const int tid = threadIdx.x;
    const int tx = tid & 15, ty = tid >> 4;
    const int lr = tid >> 1;
    const int lk = (tid & 1) * 4;
    const int la = tid >> 5;
    const int lf = (tid & 31) * 4;

    float acc[8][8];
    #pragma unroll
    for (int m = 0; m < 8; ++m)
        #pragma unroll
        for (int n = 0; n < 8; ++n) acc[m][n] = 0.f;

    const float* ep  = g_E  + ((size_t)(b*512 + c0 + lr))*512 + lk;
    const float* vp  = g_vf + ((size_t)(b*512 + la))*NPK + f0 + lf;
    const float* rdp = g_rD + b*512 + lk;

    float4 e0 = *(const float4*)(ep);
    float4 e1 = *(const float4*)(ep + 8);
    float4 r0 = *(const float4*)(rdp);
    float4 r1 = *(const float4*)(rdp + 8);
    float4 v0 = *(const float4*)(vp);
    float4 v1 = *(const float4*)(vp + (size_t)8*NPK);
    As[0][lk+0][lr]=e0.x*r0.x; As[0][lk+1][lr]=e0.y*r0.y; As[0][lk+2][lr]=e0.z*r0.z; As[0][lk+3][lr]=e0.w*r0.w;
    As[0][lk+8][lr]=e1.x*r1.x; As[0][lk+9][lr]=e1.y*r1.y; As[0][lk+10][lr]=e1.z*r1.z; As[0][lk+11][lr]=e1.w*r1.w;
    *(float4*)&Bs[0][la][lf]     = v0;
    *(float4*)&Bs[0][la + 8][lf] = v1;
    __syncthreads();

    #pragma unroll 1
    for (int t = 0; t < 32; ++t) {
        const int cur = t & 1;
        if (t < 31) {
            const int a0 = (t + 1) * 16;
            e0 = *(const float4*)(ep + a0);
            e1 = *(const float4*)(ep + a0 + 8);
            r0 = *(const float4*)(rdp + a0);
            r1 = *(const float4*)(rdp + a0 + 8);
            v0 = *(const float4*)(vp + (size_t)a0*NPK);
            v1 = *(const float4*)(vp + (size_t)(a0 + 8)*NPK);
        }
        #pragma unroll
        for (int kk = 0; kk < 16; ++kk) {
            float4 c0v = *(const float4*)&As[cur][kk][ty*4];
            float4 c1v = *(const float4*)&As[cur][kk][ty*4 + 64];
            float4 f0v = *(const float4*)&Bs[cur][kk][tx*4];
            float4 f1v = *(const float4*)&Bs[cur][kk][tx*4 + 64];
            float cm[8] = {c0v.x,c0v.y,c0v.z,c0v.w,c1v.x,c1v.y,c1v.z,c1v.w};
            float fn[8] = {f0v.x,f0v.y,f0v.z,f0v.w,f1v.x,f1v.y,f1v.z,f1v.w};
            #pragma unroll
            for (int m = 0; m < 8; ++m)
                #pragma unroll
                for (int n = 0; n < 8; ++n)
                    acc[m][n] = fmaf(cm[m], fn[n], acc[m][n]);
        }
        if (t < 31) {
            const int nxt = cur ^ 1;
            As[nxt][lk+0][lr]=e0.x*r0.x; As[nxt][lk+1][lr]=e0.y*r0.y; As[nxt][lk+2][lr]=e0.z*r0.z; As[nxt][lk+3][lr]=e0.w*r0.w;
            As[nxt][lk+8][lr]=e1.x*r1.x; As[nxt][lk+9][lr]=e1.y*r1.y; As[nxt][lk+10][lr]=e1.z*r1.z; As[nxt][lk+11][lr]=e1.w*r1.w;
            *(float4*)&Bs[nxt][la][lf]     = v0;
            *(float4*)&Bs[nxt][la + 8][lf] = v1;
            __syncthreads();
        }
    }

    /* mirrored epilogue: packed col t -> (i,j) and (j,i) */
    int fi[8], fj[8];
    bool fvalid[8];
    #pragma unroll
    for (int n = 0; n < 8; ++n) {
        int tcol = f0 + tx*4 + (n & 3) + (n >> 2)*64;
        fvalid[n] = (tcol < NTRI);
        int2 ij = g_lut[fvalid[n] ? tcol : (NTRI-1)];
        fi[n] = ij.x; fj[n] = ij.y;
    }

    #pragma unroll
    for (int m = 0; m < 8; ++m) {
        int c = c0 + ty*4 + (m & 3) + (m >> 2)*64;
        float* op = out + ((size_t)(b*512 + c))*1024;
        #pragma unroll
        for (int n = 0; n < 8; ++n) {
            if (fvalid[n]) {
                float v = acc[m][n];
                op[fi[n]*32 + fj[n]] = v;
                op[fj[n]*32 + fi[n]] = v;
            }
        }
    }
}

/* ------------- launch ------------- */
extern "C" void kernel_launch(void* const* d_in, const int* in_sizes, int n_in,
                              void* d_out, int out_size) {
    const float* x  = (const float*)d_in[0];
    const float* wq = (const float*)d_in[1];
    const float* wk = (const float*)d_in[2];
    const float* wv = (const float*)d_in[3];
    float* out = (float*)d_out;

    lut_kernel<<<2, 256>>>();
    cayley_kernel<<<3, 64>>>(wq, wk, wv);
    logm_transform_kernel<<<NMAT/WPB, WPB*32>>>(x);
    zeroD_kernel<<<NMAT/256, 256>>>();
    score_kernel<<<dim3(4, 4, NB), 256>>>();
    rcpD_kernel<<<NMAT/256, 256>>>();
    zeroDiag_kernel<<<NMAT*32/256, 256>>>(out);
    out_kernel<<<dim3(4, 4, NB), 256>>>(out);
}

// round 11
// speedup vs baseline: 8.4292x; 1.1020x over previous
#include <cuda_runtime.h>
#include <math.h>

#define NB 16
#define NN 512
#define NMAT (NB*NN)   /* 8192 matrices */
#define NSWEEP 6
#define WPB 4          /* matrices (warps) per block */
#define NPK 512        /* packed (lower-tri) stride: 496 used + 16 pad */
#define NTRI 496       /* strict lower triangle of 32x32 */

/* ------------- device scratch (allocation-free) ------------- */
__device__ float g_C[3*1024];            /* Cayley matrices Cq,Ck,Cv */
__device__ float g_B[(size_t)NMAT*1024]; /* Jacobi result columns B[i][j] */
__device__ float g_w[NMAT*32];           /* log(lam)/lam^2 weights */
__device__ float g_qf[(size_t)NMAT*NPK]; /* packed sqrt(2)*lower(q) */
__device__ float g_kf[(size_t)NMAT*NPK]; /* packed sqrt(2)*lower(k) */
__device__ float g_vf[(size_t)NMAT*NPK]; /* packed lower(v)         */
__device__ float g_q2[NMAT];
__device__ float g_k2[NMAT];
__device__ float g_E[(size_t)NB*NN*NN];  /* exp(scores)[b][j][i] */
__device__ float g_D[NMAT];              /* col sums D[b*512+i]  */
__device__ float g_rD[NMAT];             /* 1/D */
__device__ int2  g_lut[NTRI];            /* t -> (i,j), i>j */

/* ------------- LUT init: t -> (i,j) strict lower triangle ------------- */
__global__ void lut_kernel() {
    int t = blockIdx.x * blockDim.x + threadIdx.x;
    if (t >= NTRI) return;
    int i = (int)((1.0 + sqrt(1.0 + 8.0*(double)t)) * 0.5);
    while (i*(i-1)/2 > t) --i;
    while ((i+1)*i/2 <= t) ++i;
    int j = t - i*(i-1)/2;
    g_lut[t] = make_int2(i, j);
}

/* ------------- kernel A: Cayley maps C = (I-X)(I+X)^-1, X = W - W^T ------------- */
__global__ void cayley_kernel(const float* __restrict__ Wq,
                              const float* __restrict__ Wk,
                              const float* __restrict__ Wv) {
    const int w = blockIdx.x;
    const float* W = (w == 0) ? Wq : (w == 1) ? Wk : Wv;
    __shared__ float M[32][64];
    __shared__ float X[32][32];
    __shared__ float fac[32];
    __shared__ float pivv;
    __shared__ int   pivi;
    const int t = threadIdx.x;    /* 64 threads */

    for (int e = t; e < 1024; e += 64) {
        int i = e >> 5, j = e & 31;
        float xv = W[i*32 + j] - W[j*32 + i];
        X[i][j] = xv;
        M[i][j]      = ((i == j) ? 1.f : 0.f) + xv;
        M[i][j + 32] = (i == j) ? 1.f : 0.f;
    }
    __syncthreads();

    for (int k = 0; k < 32; ++k) {
        if (t == 0) {
            float best = -1.f; int bi = k;
            for (int i = k; i < 32; ++i) {
                float v = fabsf(M[i][k]);
                if (v > best) { best = v; bi = i; }
            }
            pivi = bi;
        }
        __syncthreads();
        int pi = pivi;
        if (pi != k) { float tmp = M[k][t]; M[k][t] = M[pi][t]; M[pi][t] = tmp; }
        __syncthreads();
        if (t == 0) pivv = M[k][k];
        __syncthreads();
        float pv = pivv;
        M[k][t] /= pv;
        __syncthreads();
        if (t < 32) fac[t] = M[t][k];
        __syncthreads();
        for (int i = 0; i < 32; ++i)
            if (i != k) M[i][t] -= fac[i] * M[k][t];
        __syncthreads();
    }

    for (int e = t; e < 1024; e += 64) {
        int i = e >> 5, j = e & 31;
        float acc = M[i][32 + j];
        #pragma unroll
        for (int kk = 0; kk < 32; ++kk) acc -= X[i][kk] * M[kk][32 + j];
        g_C[w*1024 + e] = acc;
    }
}

/* ------------- kernel B1: lean warp-per-matrix one-sided Jacobi ------------- */
__global__ __launch_bounds__(128, 6)
void jacobi_kernel(const float* __restrict__ x) {
    const int tid  = threadIdx.x;
    const int wp   = tid >> 5;
    const int lane = tid & 31;
    const int mat  = blockIdx.x * WPB + wp;

    const float* xin = x + (size_t)mat * 1024;
    float b[32];
    #pragma unroll
    for (int i = 0; i < 32; ++i) b[i] = xin[i*32 + lane];

    float sn = 0.f;
    #pragma unroll
    for (int i = 0; i < 32; ++i) sn = fmaf(b[i], b[i], sn);

    float pb[32];
    for (int sw = 0; sw < NSWEEP; ++sw) {
        int nrot = 0;
        for (int r = 0; r < 31; ++r) {
            int partner;
            if (lane == 31) partner = r;
            else {
                partner = (2*r + 31 - lane) % 31;
                if (partner == lane) partner = 31;
            }

            float cr0 = 0.f, cr1 = 0.f, cr2 = 0.f, cr3 = 0.f;
            #pragma unroll
            for (int i = 0; i < 32; i += 4) {
                pb[i+0] = __shfl_sync(0xffffffffu, b[i+0], partner);
                pb[i+1] = __shfl_sync(0xffffffffu, b[i+1], partner);
                pb[i+2] = __shfl_sync(0xffffffffu, b[i+2], partner);
                pb[i+3] = __shfl_sync(0xffffffffu, b[i+3], partner);
                cr0 = fmaf(b[i+0], pb[i+0], cr0);
                cr1 = fmaf(b[i+1], pb[i+1], cr1);
                cr2 = fmaf(b[i+2], pb[i+2], cr2);
                cr3 = fmaf(b[i+3], pb[i+3], cr3);
            }
            float cross = (cr0 + cr1) + (cr2 + cr3);
            float pn = __shfl_sync(0xffffffffu, sn, partner);

            bool doRot = (cross*cross > 1e-10f * sn * pn);
            if (__any_sync(0xffffffffu, doRot)) {
                ++nrot;
                bool isp = lane < partner;
                float delta = isp ? (pn - sn) : (sn - pn);

                float c = 1.f, s = 0.f;
                if (cross != 0.f) {
                    float tau = delta / (2.f * cross);
                    float tt  = copysignf(1.f, tau) / (fabsf(tau) + sqrtf(fmaf(tau, tau, 1.f)));
                    c = rsqrtf(fmaf(tt, tt, 1.f));
                    s = tt * c;
                }
                float ssgn = isp ? -s : s;
                #pragma unroll
                for (int i = 0; i < 32; ++i)
                    b[i] = fmaf(c, b[i], ssgn * pb[i]);
                sn = fmaf(c*c, sn, fmaf(s*s, pn, 2.f*c*ssgn*cross));
            }
        }
        if (nrot == 0) break;
    }

    /* exact final norm -> weight */
    sn = 0.f;
    #pragma unroll
    for (int i = 0; i < 32; ++i) sn = fmaf(b[i], b[i], sn);
    float lam = sqrtf(sn);
    float wgt = logf(lam) / sn;

    /* coalesced: lane = column j, row-major B[i][j] */
    float* bout = g_B + (size_t)mat*1024 + lane;
    #pragma unroll
    for (int i = 0; i < 32; ++i) bout[i*32] = b[i];
    g_w[mat*32 + lane] = wgt;
}

/* ------------- kernel B2: S = B diag(w) B^T (zero diag), 3 congruences, packed write ------------- */
__global__ __launch_bounds__(WPB*32)
void postproc_kernel() {
    __shared__ float Bsh[WPB][32][33];
    __shared__ float Ssh[WPB][32][33];
    __shared__ float Cs[3][32][33];
    __shared__ float wsh[WPB][32];

    const int tid  = threadIdx.x;
    const int wp   = tid >> 5;
    const int lane = tid & 31;
    const int mat  = blockIdx.x * WPB + wp;

    for (int e = tid; e < 3*1024; e += WPB*32) {
        int w = e >> 10, r = (e >> 5) & 31, cjj = e & 31;
        Cs[w][r][cjj] = g_C[e];
    }
    __syncthreads();

    {
        const float* bin = g_B + (size_t)mat*1024 + lane;
        #pragma unroll
        for (int i = 0; i < 32; ++i) Bsh[wp][i][lane] = bin[i*32];
        wsh[wp][lane] = g_w[mat*32 + lane];
    }
    __syncwarp();

    float rw[32];
    #pragma unroll
    for (int j = 0; j < 32; ++j) rw[j] = wsh[wp][j] * Bsh[wp][lane][j];
    #pragma unroll
    for (int k = 0; k < 32; ++k) {
        float acc = 0.f;
        #pragma unroll
        for (int j = 0; j < 32; ++j) acc = fmaf(rw[j], Bsh[wp][k][j], acc);
        Ssh[wp][lane][k] = (k == lane) ? 0.f : acc;
    }
    __syncwarp();

    #pragma unroll 1
    for (int wsel = 0; wsel < 3; ++wsel) {
        float crow[32];
        #pragma unroll
        for (int m = 0; m < 32; ++m) crow[m] = Cs[wsel][lane][m];

        float t[32];
        #pragma unroll
        for (int k = 0; k < 32; ++k) {
            float acc = 0.f;
            #pragma unroll
            for (int m = 0; m < 32; ++m) acc = fmaf(crow[m], Ssh[wp][m][k], acc);
            t[k] = acc;
        }

        float ss = 0.f;
        #pragma unroll
        for (int k = 0; k < 32; ++k) {
            float acc = 0.f;
            #pragma unroll
            for (int m = 0; m < 32; ++m) acc = fmaf(t[m], Cs[wsel][k][m], acc);
            if (k == lane) acc = 0.f;
            ss = fmaf(acc, acc, ss);
            Bsh[wp][lane][k] = acc;       /* overwrite B stage with Y (B dead) */
        }
        __syncwarp();

        float* gout = (wsel == 0) ? g_qf : (wsel == 1) ? g_kf : g_vf;
        const float scale = (wsel < 2) ? 1.41421356237309515f : 1.f;
        #pragma unroll
        for (int t2 = lane; t2 < NPK; t2 += 32) {
            float val = 0.f;
            if (t2 < NTRI) {
                int2 ij = g_lut[t2];
                val = scale * Bsh[wp][ij.x][ij.y];
            }
            gout[(size_t)mat*NPK + t2] = val;
        }

        if (wsel < 2) {
            #pragma unroll
            for (int off = 16; off; off >>= 1)
                ss += __shfl_down_sync(0xffffffffu, ss, off);
            if (lane == 0) ((wsel == 0) ? g_q2 : g_k2)[mat] = ss;
        }
        __syncwarp();

        /* B stage must be restored? No: rw[] already captured, Ssh persists;
           only Bsh was consumed. Ssh is the sole input to later wsel. */
    }
}

/* ------------- kernel: zero D ------------- */
__global__ void zeroD_kernel() {
    int i = blockIdx.x * blockDim.x + threadIdx.x;
    if (i < NMAT) g_D[i] = 0.f;
}

/* ------------- kernel: rD = 1/D ------------- */
__global__ void rcpD_kernel() {
    int i = blockIdx.x * blockDim.x + threadIdx.x;
    if (i < NMAT) g_rD[i] = 1.f / g_D[i];
}

/* ------------- kernel: zero diagonal of output ------------- */
__global__ void zeroDiag_kernel(float* __restrict__ out) {
    int t = blockIdx.x * blockDim.x + threadIdx.x;   /* NMAT*32 threads */
    int m = t >> 5, d = t & 31;
    out[(size_t)m*1024 + d*33] = 0.f;
}

/* ------------- kernel C: 128x128 tile, 8x8/thread, packed K=512, double-buffered ------------- */
__global__ __launch_bounds__(256, 2)
void score_kernel() {
    const int b  = blockIdx.z;
    const int i0 = blockIdx.x * 128;
    const int j0 = blockIdx.y * 128;
    __shared__ float Ks[2][16][132];
    __shared__ float Qs[2][16][132];
    __shared__ float scol[128];
    const int tid = threadIdx.x;
    const int tx = tid & 15, ty = tid >> 4;
    const int lr = tid >> 1;
    const int lk = (tid & 1) * 4;

    float acc[8][8];
    #pragma unroll
    for (int m = 0; m < 8; ++m)
        #pragma unroll
        for (int n = 0; n < 8; ++n) acc[m][n] = 0.f;
    if (tid < 128) scol[tid] = 0.f;

    const float* kp = g_kf + ((size_t)(b*512 + j0 + lr))*NPK + lk;
    const float* qp = g_qf + ((size_t)(b*512 + i0 + lr))*NPK + lk;

    float4 kv0 = *(const float4*)(kp);
    float4 kv1 = *(const float4*)(kp + 8);
    float4 qv0 = *(const float4*)(qp);
    float4 qv1 = *(const float4*)(qp + 8);
    Ks[0][lk+0][lr]=kv0.x; Ks[0][lk+1][lr]=kv0.y; Ks[0][lk+2][lr]=kv0.z; Ks[0][lk+3][lr]=kv0.w;
    Ks[0][lk+8][lr]=kv1.x; Ks[0][lk+9][lr]=kv1.y; Ks[0][lk+10][lr]=kv1.z; Ks[0][lk+11][lr]=kv1.w;
    Qs[0][lk+0][lr]=qv0.x; Qs[0][lk+1][lr]=qv0.y; Qs[0][lk+2][lr]=qv0.z; Qs[0][lk+3][lr]=qv0.w;
    Qs[0][lk+8][lr]=qv1.x; Qs[0][lk+9][lr]=qv1.y; Qs[0][lk+10][lr]=qv1.z; Qs[0][lk+11][lr]=qv1.w;
    __syncthreads();

    #pragma unroll 1
    for (int t = 0; t < 32; ++t) {
        const int cur = t & 1;
        if (t < 31) {
            const int k0 = (t + 1) * 16;
            kv0 = *(const float4*)(kp + k0);
            kv1 = *(const float4*)(kp + k0 + 8);
            qv0 = *(const float4*)(qp + k0);
            qv1 = *(const float4*)(qp + k0 + 8);
        }
        #pragma unroll
        for (int kk = 0; kk < 16; ++kk) {
            float4 a0 = *(const float4*)&Qs[cur][kk][tx*4];
            float4 a1 = *(const float4*)&Qs[cur][kk][tx*4 + 64];
            float4 b0 = *(const float4*)&Ks[cur][kk][ty*4];
            float4 b1 = *(const float4*)&Ks[cur][kk][ty*4 + 64];
            float av[8] = {a0.x,a0.y,a0.z,a0.w,a1.x,a1.y,a1.z,a1.w};
            float bv[8] = {b0.x,b0.y,b0.z,b0.w,b1.x,b1.y,b1.z,b1.w};
            #pragma unroll
            for (int m = 0; m < 8; ++m)
                #pragma unroll
                for (int n = 0; n < 8; ++n)
                    acc[m][n] = fmaf(bv[m], av[n], acc[m][n]);
        }
        if (t < 31) {
            const int nxt = cur ^ 1;
            Ks[nxt][lk+0][lr]=kv0.x; Ks[nxt][lk+1][lr]=kv0.y; Ks[nxt][lk+2][lr]=kv0.z; Ks[nxt][lk+3][lr]=kv0.w;
            Ks[nxt][lk+8][lr]=kv1.x; Ks[nxt][lk+9][lr]=kv1.y; Ks[nxt][lk+10][lr]=kv1.z; Ks[nxt][lk+11][lr]=kv1.w;
            Qs[nxt][lk+0][lr]=qv0.x; Qs[nxt][lk+1][lr]=qv0.y; Qs[nxt][lk+2][lr]=qv0.z; Qs[nxt][lk+3][lr]=qv0.w;
            Qs[nxt][lk+8][lr]=qv1.x; Qs[nxt][lk+9][lr]=qv1.y; Qs[nxt][lk+10][lr]=qv1.z; Qs[nxt][lk+11][lr]=qv1.w;
            __syncthreads();
        }
    }

    float q2c[8], k2r[8];
    #pragma unroll
    for (int n = 0; n < 8; ++n)
        q2c[n] = g_q2[b*512 + i0 + tx*4 + (n & 3) + (n >> 2)*64];
    #pragma unroll
    for (int m = 0; m < 8; ++m)
        k2r[m] = g_k2[b*512 + j0 + ty*4 + (m & 3) + (m >> 2)*64];

    float csum[8];
    #pragma unroll
    for (int n = 0; n < 8; ++n) csum[n] = 0.f;

    #pragma unroll
    for (int m = 0; m < 8; ++m) {
        int j = j0 + ty*4 + (m & 3) + (m >> 2)*64;
        float ev[8];
        #pragma unroll
        for (int n = 0; n < 8; ++n) {
            float d2 = k2r[m] + q2c[n] - 2.f * acc[m][n];
            d2 = fmaxf(d2, 1e-12f);
            float en = sqrtf(d2);
            float sc = 1.f / (1.f + __logf(1.f + en));
            ev[n] = __expf(sc);
            csum[n] += ev[n];
        }
        float* ep = g_E + ((size_t)b*512 + j)*512 + i0 + tx*4;
        float4 o0; o0.x = ev[0]; o0.y = ev[1]; o0.z = ev[2]; o0.w = ev[3];
        float4 o1; o1.x = ev[4]; o1.y = ev[5]; o1.z = ev[6]; o1.w = ev[7];
        *(float4*)ep = o0;
        *(float4*)(ep + 64) = o1;
    }

    #pragma unroll
    for (int n = 0; n < 8; ++n)
        atomicAdd(&scol[tx*4 + (n & 3) + (n >> 2)*64], csum[n]);
    __syncthreads();
    if (tid < 128) atomicAdd(&g_D[b*512 + i0 + tid], scol[tid]);
}

/* ------------- kernel D: out = E*diag(rD)*Vpacked, mirrored epilogue ------------- */
__global__ __launch_bounds__(256, 2)
void out_kernel(float* __restrict__ out) {
    const int b  = blockIdx.z;
    const int c0 = blockIdx.x * 128;
    const int f0 = blockIdx.y * 128;
    __shared__ float As[2][16][132];
    __shared__ float Bs[2][16][132];
    const int tid = threadIdx.x;
    const int tx = tid & 15, ty = tid >> 4;
    const int lr = tid >> 1;
    const int lk = (tid & 1) * 4;
    const int la = tid >> 5;
    const int lf = (tid & 31) * 4;

    float acc[8][8];
    #pragma unroll
    for (int m = 0; m < 8; ++m)
        #pragma unroll
        for (int n = 0; n < 8; ++n) acc[m][n] = 0.f;

    const float* ep  = g_E  + ((size_t)(b*512 + c0 + lr))*512 + lk;
    const float* vp  = g_vf + ((size_t)(b*512 + la))*NPK + f0 + lf;
    const float* rdp = g_rD + b*512 + lk;

    float4 e0 = *(const float4*)(ep);
    float4 e1 = *(const float4*)(ep + 8);
    float4 r0 = *(const float4*)(rdp);
    float4 r1 = *(const float4*)(rdp + 8);
    float4 v0 = *(const float4*)(vp);
    float4 v1 = *(const float4*)(vp + (size_t)8*NPK);
    As[0][lk+0][lr]=e0.x*r0.x; As[0][lk+1][lr]=e0.y*r0.y; As[0][lk+2][lr]=e0.z*r0.z; As[0][lk+3][lr]=e0.w*r0.w;
    As[0][lk+8][lr]=e1.x*r1.x; As[0][lk+9][lr]=e1.y*r1.y; As[0][lk+10][lr]=e1.z*r1.z; As[0][lk+11][lr]=e1.w*r1.w;
    *(float4*)&Bs[0][la][lf]     = v0;
    *(float4*)&Bs[0][la + 8][lf] = v1;
    __syncthreads();

    #pragma unroll 1
    for (int t = 0; t < 32; ++t) {
        const int cur = t & 1;
        if (t < 31) {
            const int a0 = (t + 1) * 16;
            e0 = *(const float4*)(ep + a0);
            e1 = *(const float4*)(ep + a0 + 8);
            r0 = *(const float4*)(rdp + a0);
            r1 = *(const float4*)(rdp + a0 + 8);
            v0 = *(const float4*)(vp + (size_t)a0*NPK);
            v1 = *(const float4*)(vp + (size_t)(a0 + 8)*NPK);
        }
        #pragma unroll
        for (int kk = 0; kk < 16; ++kk) {
            float4 c0v = *(const float4*)&As[cur][kk][ty*4];
            float4 c1v = *(const float4*)&As[cur][kk][ty*4 + 64];
            float4 f0v = *(const float4*)&Bs[cur][kk][tx*4];
            float4 f1v = *(const float4*)&Bs[cur][kk][tx*4 + 64];
            float cm[8] = {c0v.x,c0v.y,c0v.z,c0v.w,c1v.x,c1v.y,c1v.z,c1v.w};
            float fn[8] = {f0v.x,f0v.y,f0v.z,f0v.w,f1v.x,f1v.y,f1v.z,f1v.w};
            #pragma unroll
            for (int m = 0; m < 8; ++m)
                #pragma unroll
                for (int n = 0; n < 8; ++n)
                    acc[m][n] = fmaf(cm[m], fn[n], acc[m][n]);
        }
        if (t < 31) {
            const int nxt = cur ^ 1;
            As[nxt][lk+0][lr]=e0.x*r0.x; As[nxt][lk+1][lr]=e0.y*r0.y; As[nxt][lk+2][lr]=e0.z*r0.z; As[nxt][lk+3][lr]=e0.w*r0.w;
            As[nxt][lk+8][lr]=e1.x*r1.x; As[nxt][lk+9][lr]=e1.y*r1.y; As[nxt][lk+10][lr]=e1.z*r1.z; As[nxt][lk+11][lr]=e1.w*r1.w;
            *(float4*)&Bs[nxt][la][lf]     = v0;
            *(float4*)&Bs[nxt][la + 8][lf] = v1;
            __syncthreads();
        }
    }

    int fi[8], fj[8];
    bool fvalid[8];
    #pragma unroll
    for (int n = 0; n < 8; ++n) {
        int tcol = f0 + tx*4 + (n & 3) + (n >> 2)*64;
        fvalid[n] = (tcol < NTRI);
        int2 ij = g_lut[fvalid[n] ? tcol : (NTRI-1)];
        fi[n] = ij.x; fj[n] = ij.y;
    }

    #pragma unroll
    for (int m = 0; m < 8; ++m) {
        int c = c0 + ty*4 + (m & 3) + (m >> 2)*64;
        float* op = out + ((size_t)(b*512 + c))*1024;
        #pragma unroll
        for (int n = 0; n < 8; ++n) {
            if (fvalid[n]) {
                float v = acc[m][n];
                op[fi[n]*32 + fj[n]] = v;
                op[fj[n]*32 + fi[n]] = v;
            }
        }
    }
}

/* ------------- launch ------------- */
extern "C" void kernel_launch(void* const* d_in, const int* in_sizes, int n_in,
                              void* d_out, int out_size) {
    const float* x  = (const float*)d_in[0];
    const float* wq = (const float*)d_in[1];
    const float* wk = (const float*)d_in[2];
    const float* wv = (const float*)d_in[3];
    float* out = (float*)d_out;

    lut_kernel<<<2, 256>>>();
    cayley_kernel<<<3, 64>>>(wq, wk, wv);
    jacobi_kernel<<<NMAT/WPB, WPB*32>>>(x);
    postproc_kernel<<<NMAT/WPB, WPB*32>>>();
    zeroD_kernel<<<NMAT/256, 256>>>();
    score_kernel<<<dim3(4, 4, NB), 256>>>();
    rcpD_kernel<<<NMAT/256, 256>>>();
    zeroDiag_kernel<<<NMAT*32/256, 256>>>(out);
    out_kernel<<<dim3(4, 4, NB), 256>>>(out);
}